// round 2
// baseline (speedup 1.0000x reference)
#include <cuda_runtime.h>
#include <cstdint>

#define NN 100000
#define NE 1600000
#define DD 128

// ------------------------- scratch (device globals; no allocs allowed) -----
__device__ float g_X  [(size_t)NN * DD];   // 51.2 MB feature buffer
__device__ float g_AGG[(size_t)NN * DD];   // 51.2 MB aggregation buffer
__device__ float g_ns [NN];                // norm_src (also used as deg_out accumulator)
__device__ float g_nd [NN];                // norm_dst (also used as deg_in accumulator)
__device__ float g_vec[DD];                // final column-sum vector

// ------------------------- degree accumulation -----------------------------
__global__ void deg_kernel(const int* __restrict__ src,
                           const int* __restrict__ dst,
                           float* __restrict__ dsrc, float* __restrict__ ddst) {
    int i = blockIdx.x * blockDim.x + threadIdx.x;
    if (i < NE) {
        atomicAdd(&dsrc[src[i]], 1.0f);
        atomicAdd(&ddst[dst[i]], 1.0f);
    }
}

// deg -> deg^{-1/2} (with clamp at 1), in place, both arrays
__global__ void norm_kernel(float* __restrict__ a, float* __restrict__ b) {
    int i = blockIdx.x * blockDim.x + threadIdx.x;
    if (i < NN) {
        a[i] = rsqrtf(fmaxf(a[i], 1.0f));
        b[i] = rsqrtf(fmaxf(b[i], 1.0f));
    }
}

// X = h * norm_src[row]  (vectorized float4)
__global__ void scale_kernel(const float* __restrict__ h,
                             const float* __restrict__ ns,
                             float* __restrict__ X) {
    int i = blockIdx.x * blockDim.x + threadIdx.x;           // float4 index
    int total = NN * DD / 4;
    if (i < total) {
        int row = i >> 5;                                    // 32 float4 per row
        float s = ns[row];
        float4 v = ((const float4*)h)[i];
        v.x *= s; v.y *= s; v.z *= s; v.w *= s;
        ((float4*)X)[i] = v;
    }
}

// ------------------------- SpMM scatter: AGG[dst] += X[src] ----------------
// one warp per edge; lane l handles floats [4l, 4l+4) via red.global.add.v4.f32
__global__ void scatter_kernel(const float* __restrict__ X,
                               float* __restrict__ AGG,
                               const int* __restrict__ src,
                               const int* __restrict__ dst) {
    int gtid = blockIdx.x * blockDim.x + threadIdx.x;
    int e    = gtid >> 5;
    int lane = gtid & 31;
    if (e >= NE) return;
    int s = src[e];
    int d = dst[e];
    const float4 v = *(const float4*)(X + (size_t)s * DD + lane * 4);
    float* p = AGG + (size_t)d * DD + lane * 4;
    asm volatile("red.global.add.v4.f32 [%0], {%1, %2, %3, %4};"
                 :: "l"(p), "f"(v.x), "f"(v.y), "f"(v.z), "f"(v.w)
                 : "memory");
}

// ------------------------- fused GEMM + epilogue ---------------------------
// Out[m, :] = epi( (AGG[m, :] * nd[m]) @ W + b )   with epi = relu?, *ns[m]?
// BM=64, BN=128, BK=16, thread tile 4x8, 256 threads/block
template <bool RELU, bool SCALE_OUT>
__global__ __launch_bounds__(256)
void gemm_kernel(const float* __restrict__ A, const float* __restrict__ W,
                 const float* __restrict__ bias,
                 const float* __restrict__ nd, const float* __restrict__ ns,
                 float* __restrict__ Out) {
    __shared__ float As[16][64 + 4];
    __shared__ float Ws[16][128];

    const int t   = threadIdx.x;
    const int tm  = t >> 4;          // 0..15 row-group
    const int tn  = t & 15;          // 0..15 col-group
    const int row0 = blockIdx.x * 64;

    float acc[4][8];
#pragma unroll
    for (int r = 0; r < 4; r++)
#pragma unroll
        for (int c = 0; c < 8; c++) acc[r][c] = 0.0f;

    const int ar  = t >> 2;          // 0..63  (A-load row within tile)
    const int ak4 = (t & 3) * 4;     // 0,4,8,12

    for (int kt = 0; kt < DD; kt += 16) {
        // load A tile (64 x 16), transposed into As[k][m]
        {
            int grow = row0 + ar;
            float4 v = make_float4(0.f, 0.f, 0.f, 0.f);
            if (grow < NN)
                v = *(const float4*)(A + (size_t)grow * DD + kt + ak4);
            As[ak4 + 0][ar] = v.x;
            As[ak4 + 1][ar] = v.y;
            As[ak4 + 2][ar] = v.z;
            As[ak4 + 3][ar] = v.w;
        }
        // load W tile (16 x 128)
#pragma unroll
        for (int j = 0; j < 2; j++) {
            int idx = t + j * 256;
            int wk  = idx >> 5;
            int wn4 = (idx & 31) * 4;
            *(float4*)&Ws[wk][wn4] = *(const float4*)(W + (size_t)(kt + wk) * DD + wn4);
        }
        __syncthreads();

#pragma unroll
        for (int k = 0; k < 16; k++) {
            float a0 = As[k][tm * 4 + 0];
            float a1 = As[k][tm * 4 + 1];
            float a2 = As[k][tm * 4 + 2];
            float a3 = As[k][tm * 4 + 3];
            float4 w0 = *(const float4*)&Ws[k][tn * 8];
            float4 w1 = *(const float4*)&Ws[k][tn * 8 + 4];
            float wv[8] = {w0.x, w0.y, w0.z, w0.w, w1.x, w1.y, w1.z, w1.w};
#pragma unroll
            for (int c = 0; c < 8; c++) {
                acc[0][c] = fmaf(a0, wv[c], acc[0][c]);
                acc[1][c] = fmaf(a1, wv[c], acc[1][c]);
                acc[2][c] = fmaf(a2, wv[c], acc[2][c]);
                acc[3][c] = fmaf(a3, wv[c], acc[3][c]);
            }
        }
        __syncthreads();
    }

    // epilogue
#pragma unroll
    for (int r = 0; r < 4; r++) {
        int row = row0 + tm * 4 + r;
        if (row >= NN) continue;
        float sd = nd[row];
        float so = SCALE_OUT ? ns[row] : 1.0f;
        float4 o0, o1;
#pragma unroll
        for (int c = 0; c < 8; c++) {
            int n = tn * 8 + c;
            float v = acc[r][c] * sd + bias[n];
            if (RELU) v = fmaxf(v, 0.0f);
            v *= so;
            if (c < 4) ((float*)&o0)[c] = v; else ((float*)&o1)[c - 4] = v;
        }
        float* outp = Out + (size_t)row * DD + tn * 8;
        *(float4*)(outp)     = o0;
        *(float4*)(outp + 4) = o1;
    }
}

// ------------------------- final reduce: vec[c] = sum_r AGG[r][c]*nd[r] ----
#define RED_ROWS 256
__global__ void reduce_kernel(const float* __restrict__ AGG,
                              const float* __restrict__ nd,
                              float* __restrict__ vec) {
    int c  = threadIdx.x;                 // 128 threads: one column each
    int r0 = blockIdx.x * RED_ROWS;
    float s = 0.0f;
    int rend = min(r0 + RED_ROWS, NN);
    for (int r = r0; r < rend; r++)
        s = fmaf(AGG[(size_t)r * DD + c], nd[r], s);
    atomicAdd(&vec[c], s);
}

// ------------------------- final micro-GEMM: out = (vec/N) @ W2 + b2 -------
__global__ void final_kernel(const float* __restrict__ W2,
                             const float* __restrict__ b2,
                             const float* __restrict__ vec,
                             float* __restrict__ out) {
    __shared__ float v[DD];
    int c = threadIdx.x;
    v[c] = vec[c] * (1.0f / (float)NN);
    __syncthreads();
    float acc = b2[c];
#pragma unroll 8
    for (int k = 0; k < DD; k++)
        acc = fmaf(v[k], W2[(size_t)k * DD + c], acc);
    out[c] = acc;
}

// ===========================================================================
extern "C" void kernel_launch(void* const* d_in, const int* in_sizes, int n_in,
                              void* d_out, int out_size) {
    const float* h   = (const float*)d_in[0];
    const int*   src = (const int*)d_in[1];   // JAX silently demotes int64 -> int32
    const int*   dst = (const int*)d_in[2];
    const float* W0 = (const float*)d_in[3];
    const float* b0 = (const float*)d_in[4];
    const float* W1 = (const float*)d_in[5];
    const float* b1 = (const float*)d_in[6];
    const float* W2 = (const float*)d_in[7];
    const float* b2 = (const float*)d_in[8];
    float* out = (float*)d_out;

    void *pX, *pAGG, *pns, *pnd, *pvec;
    cudaGetSymbolAddress(&pX,   g_X);
    cudaGetSymbolAddress(&pAGG, g_AGG);
    cudaGetSymbolAddress(&pns,  g_ns);
    cudaGetSymbolAddress(&pnd,  g_nd);
    cudaGetSymbolAddress(&pvec, g_vec);
    float* X   = (float*)pX;
    float* AGG = (float*)pAGG;
    float* ns  = (float*)pns;
    float* nd  = (float*)pnd;
    float* vec = (float*)pvec;

    const size_t featBytes = (size_t)NN * DD * sizeof(float);

    // --- degrees & norms ---
    cudaMemsetAsync(ns, 0, NN * sizeof(float));
    cudaMemsetAsync(nd, 0, NN * sizeof(float));
    deg_kernel<<<(NE + 255) / 256, 256>>>(src, dst, ns, nd);
    norm_kernel<<<(NN + 255) / 256, 256>>>(ns, nd);

    // --- X = h * norm_src ---
    scale_kernel<<<(NN * DD / 4 + 255) / 256, 256>>>(h, ns, X);

    const int scatterBlocks = (int)(((size_t)NE * 32 + 255) / 256);
    const int gemmBlocks    = (NN + 63) / 64;

    // --- layer 0: AGG = A @ X ; X = relu(AGG*nd @ W0 + b0) * ns ---
    cudaMemsetAsync(AGG, 0, featBytes);
    scatter_kernel<<<scatterBlocks, 256>>>(X, AGG, src, dst);
    gemm_kernel<true, true><<<gemmBlocks, 256>>>(AGG, W0, b0, nd, ns, X);

    // --- layer 1 ---
    cudaMemsetAsync(AGG, 0, featBytes);
    scatter_kernel<<<scatterBlocks, 256>>>(X, AGG, src, dst);
    gemm_kernel<true, true><<<gemmBlocks, 256>>>(AGG, W1, b1, nd, ns, X);

    // --- layer 2 (GEMM folded through the mean) ---
    cudaMemsetAsync(AGG, 0, featBytes);
    scatter_kernel<<<scatterBlocks, 256>>>(X, AGG, src, dst);
    cudaMemsetAsync(vec, 0, DD * sizeof(float));
    reduce_kernel<<<(NN + RED_ROWS - 1) / RED_ROWS, DD>>>(AGG, nd, vec);
    final_kernel<<<1, DD>>>(W2, b2, vec, out);

    (void)in_sizes; (void)n_in; (void)out_size;
}

// round 3
// speedup vs baseline: 1.5205x; 1.5205x over previous
#include <cuda_runtime.h>
#include <cstdint>

#define NN 100000
#define NE 1600000
#define DD 128

// ------------------------- scratch (device globals) ------------------------
__device__ float g_X   [(size_t)NN * DD];  // layer output features
__device__ float g_AGG [(size_t)NN * DD];  // aggregated (pre-GEMM) features
__device__ float g_ns  [NN];
__device__ float g_nd  [NN];
__device__ int   g_cnts[NN];               // out-degree (src) histogram
__device__ int   g_cntd[NN];               // in-degree (dst) histogram
__device__ int   g_incl[NN];               // inclusive scan of g_cntd
__device__ int   g_cur [NN];               // fill cursors
__device__ int   g_esrc[NE];               // CSR-by-dst: src node per slot
__device__ int   g_bsum[128];              // block sums for scan
__device__ float g_vec [DD];               // final column-sum vector

// ------------------------- histogram ---------------------------------------
__global__ void hist_kernel(const int* __restrict__ src,
                            const int* __restrict__ dst,
                            int* __restrict__ cs, int* __restrict__ cd) {
    int i = blockIdx.x * blockDim.x + threadIdx.x;
    if (i < NE) {
        atomicAdd(&cs[src[i]], 1);
        atomicAdd(&cd[dst[i]], 1);
    }
}

// deg -> deg^{-1/2} with clamp at 1
__global__ void norm_kernel(const int* __restrict__ cs, const int* __restrict__ cd,
                            float* __restrict__ ns, float* __restrict__ nd) {
    int i = blockIdx.x * blockDim.x + threadIdx.x;
    if (i < NN) {
        ns[i] = rsqrtf(fmaxf((float)cs[i], 1.0f));
        nd[i] = rsqrtf(fmaxf((float)cd[i], 1.0f));
    }
}

// ------------------------- scan (3 kernels, chunk=1024) --------------------
__global__ void scan1_kernel(const int* __restrict__ cnt,
                             int* __restrict__ incl, int* __restrict__ bsum) {
    __shared__ int s[256];
    int b = blockIdx.x, t = threadIdx.x;
    int base = b * 1024 + t * 4;
    int v0 = (base + 0 < NN) ? cnt[base + 0] : 0;
    int v1 = (base + 1 < NN) ? cnt[base + 1] : 0;
    int v2 = (base + 2 < NN) ? cnt[base + 2] : 0;
    int v3 = (base + 3 < NN) ? cnt[base + 3] : 0;
    int l1 = v0 + v1, l2 = l1 + v2, l3 = l2 + v3;
    s[t] = l3;
    __syncthreads();
    for (int off = 1; off < 256; off <<= 1) {
        int x = (t >= off) ? s[t - off] : 0;
        __syncthreads();
        s[t] += x;
        __syncthreads();
    }
    int prev = t ? s[t - 1] : 0;
    if (base + 0 < NN) incl[base + 0] = prev + v0;
    if (base + 1 < NN) incl[base + 1] = prev + l1;
    if (base + 2 < NN) incl[base + 2] = prev + l2;
    if (base + 3 < NN) incl[base + 3] = prev + l3;
    if (t == 255) bsum[b] = s[255];
}

__global__ void scan2_kernel(int* __restrict__ bsum, int nb) {
    if (threadIdx.x == 0) {
        int acc = 0;
        for (int i = 0; i < nb; i++) { int x = bsum[i]; bsum[i] = acc; acc += x; }
    }
}

// incl += bsum[chunk]; also emit cursor = exclusive start
__global__ void scan3_kernel(int* __restrict__ incl, const int* __restrict__ bsum,
                             const int* __restrict__ cnt, int* __restrict__ cur) {
    int i = blockIdx.x * blockDim.x + threadIdx.x;
    if (i < NN) {
        int v = incl[i] + bsum[i >> 10];
        incl[i] = v;
        cur[i]  = v - cnt[i];
    }
}

// counting-sort fill of CSR (order within a segment is arbitrary; sum order only)
__global__ void fill_kernel(const int* __restrict__ src, const int* __restrict__ dst,
                            int* __restrict__ cur, int* __restrict__ esrc) {
    int i = blockIdx.x * blockDim.x + threadIdx.x;
    if (i < NE) {
        int pos = atomicAdd(&cur[dst[i]], 1);
        esrc[pos] = src[i];
    }
}

// ------------------------- gather SpMM -------------------------------------
// One warp per dst node: acc = sum_{e in in(d)} ns[src]*X[src]; then *nd[d].
// MODE 0: store to AGG.  MODE 1: accumulate column sums into vec (layer 2).
template <int MODE>
__global__ void gather_kernel(const float* __restrict__ Xin,
                              const float* __restrict__ ns,
                              const float* __restrict__ nd,
                              const int* __restrict__ incl,
                              const int* __restrict__ cnt,
                              const int* __restrict__ esrc,
                              float* __restrict__ outp) {
    const int lane  = threadIdx.x & 31;
    const int warp0 = (blockIdx.x * blockDim.x + threadIdx.x) >> 5;
    const int nwarp = (gridDim.x * blockDim.x) >> 5;
    const float4* __restrict__ Xv = (const float4*)Xin;

    float4 tot = make_float4(0.f, 0.f, 0.f, 0.f);

    for (int node = warp0; node < NN; node += nwarp) {
        int end = incl[node];
        int beg = end - cnt[node];
        float4 acc = make_float4(0.f, 0.f, 0.f, 0.f);
        int e = beg;
        for (; e + 4 <= end; e += 4) {
            int s0 = esrc[e], s1 = esrc[e + 1], s2 = esrc[e + 2], s3 = esrc[e + 3];
            float n0 = ns[s0], n1 = ns[s1], n2 = ns[s2], n3 = ns[s3];
            float4 v0 = Xv[(size_t)s0 * 32 + lane];
            float4 v1 = Xv[(size_t)s1 * 32 + lane];
            float4 v2 = Xv[(size_t)s2 * 32 + lane];
            float4 v3 = Xv[(size_t)s3 * 32 + lane];
            acc.x = fmaf(v0.x, n0, acc.x); acc.y = fmaf(v0.y, n0, acc.y);
            acc.z = fmaf(v0.z, n0, acc.z); acc.w = fmaf(v0.w, n0, acc.w);
            acc.x = fmaf(v1.x, n1, acc.x); acc.y = fmaf(v1.y, n1, acc.y);
            acc.z = fmaf(v1.z, n1, acc.z); acc.w = fmaf(v1.w, n1, acc.w);
            acc.x = fmaf(v2.x, n2, acc.x); acc.y = fmaf(v2.y, n2, acc.y);
            acc.z = fmaf(v2.z, n2, acc.z); acc.w = fmaf(v2.w, n2, acc.w);
            acc.x = fmaf(v3.x, n3, acc.x); acc.y = fmaf(v3.y, n3, acc.y);
            acc.z = fmaf(v3.z, n3, acc.z); acc.w = fmaf(v3.w, n3, acc.w);
        }
        for (; e < end; e++) {
            int s = esrc[e];
            float n = ns[s];
            float4 v = Xv[(size_t)s * 32 + lane];
            acc.x = fmaf(v.x, n, acc.x); acc.y = fmaf(v.y, n, acc.y);
            acc.z = fmaf(v.z, n, acc.z); acc.w = fmaf(v.w, n, acc.w);
        }
        float sd = nd[node];
        acc.x *= sd; acc.y *= sd; acc.z *= sd; acc.w *= sd;
        if (MODE == 0) {
            ((float4*)outp)[(size_t)node * 32 + lane] = acc;
        } else {
            tot.x += acc.x; tot.y += acc.y; tot.z += acc.z; tot.w += acc.w;
        }
    }
    if (MODE == 1) {
        float* vp = outp + lane * 4;
        atomicAdd(vp + 0, tot.x);
        atomicAdd(vp + 1, tot.y);
        atomicAdd(vp + 2, tot.z);
        atomicAdd(vp + 3, tot.w);
    }
}

// ------------------------- fused GEMM + epilogue ---------------------------
// Out = relu(A @ W + b); A is already nd-scaled; ns applied at next gather.
__global__ __launch_bounds__(256)
void gemm_kernel(const float* __restrict__ A, const float* __restrict__ W,
                 const float* __restrict__ bias, float* __restrict__ Out) {
    __shared__ float As[16][64 + 4];
    __shared__ float Ws[16][128];

    const int t    = threadIdx.x;
    const int tm   = t >> 4;
    const int tn   = t & 15;
    const int row0 = blockIdx.x * 64;

    float acc[4][8];
#pragma unroll
    for (int r = 0; r < 4; r++)
#pragma unroll
        for (int c = 0; c < 8; c++) acc[r][c] = 0.0f;

    const int ar  = t >> 2;
    const int ak4 = (t & 3) * 4;

    for (int kt = 0; kt < DD; kt += 16) {
        {
            int grow = row0 + ar;
            float4 v = make_float4(0.f, 0.f, 0.f, 0.f);
            if (grow < NN)
                v = *(const float4*)(A + (size_t)grow * DD + kt + ak4);
            As[ak4 + 0][ar] = v.x;
            As[ak4 + 1][ar] = v.y;
            As[ak4 + 2][ar] = v.z;
            As[ak4 + 3][ar] = v.w;
        }
#pragma unroll
        for (int j = 0; j < 2; j++) {
            int idx = t + j * 256;
            int wk  = idx >> 5;
            int wn4 = (idx & 31) * 4;
            *(float4*)&Ws[wk][wn4] = *(const float4*)(W + (size_t)(kt + wk) * DD + wn4);
        }
        __syncthreads();

#pragma unroll
        for (int k = 0; k < 16; k++) {
            float a0 = As[k][tm * 4 + 0];
            float a1 = As[k][tm * 4 + 1];
            float a2 = As[k][tm * 4 + 2];
            float a3 = As[k][tm * 4 + 3];
            float4 w0 = *(const float4*)&Ws[k][tn * 8];
            float4 w1 = *(const float4*)&Ws[k][tn * 8 + 4];
            float wv[8] = {w0.x, w0.y, w0.z, w0.w, w1.x, w1.y, w1.z, w1.w};
#pragma unroll
            for (int c = 0; c < 8; c++) {
                acc[0][c] = fmaf(a0, wv[c], acc[0][c]);
                acc[1][c] = fmaf(a1, wv[c], acc[1][c]);
                acc[2][c] = fmaf(a2, wv[c], acc[2][c]);
                acc[3][c] = fmaf(a3, wv[c], acc[3][c]);
            }
        }
        __syncthreads();
    }

#pragma unroll
    for (int r = 0; r < 4; r++) {
        int row = row0 + tm * 4 + r;
        if (row >= NN) continue;
        float4 o0, o1;
#pragma unroll
        for (int c = 0; c < 8; c++) {
            float v = fmaxf(acc[r][c] + bias[tn * 8 + c], 0.0f);
            if (c < 4) ((float*)&o0)[c] = v; else ((float*)&o1)[c - 4] = v;
        }
        float* outp = Out + (size_t)row * DD + tn * 8;
        *(float4*)(outp)     = o0;
        *(float4*)(outp + 4) = o1;
    }
}

// ------------------------- final micro-GEMM: out = (vec/N) @ W2 + b2 -------
__global__ void final_kernel(const float* __restrict__ W2,
                             const float* __restrict__ b2,
                             const float* __restrict__ vec,
                             float* __restrict__ out) {
    __shared__ float v[DD];
    int c = threadIdx.x;
    v[c] = vec[c] * (1.0f / (float)NN);
    __syncthreads();
    float acc = b2[c];
#pragma unroll 8
    for (int k = 0; k < DD; k++)
        acc = fmaf(v[k], W2[(size_t)k * DD + c], acc);
    out[c] = acc;
}

// ===========================================================================
extern "C" void kernel_launch(void* const* d_in, const int* in_sizes, int n_in,
                              void* d_out, int out_size) {
    const float* h   = (const float*)d_in[0];
    const int*   src = (const int*)d_in[1];   // JAX demotes int64 -> int32
    const int*   dst = (const int*)d_in[2];
    const float* W0 = (const float*)d_in[3];
    const float* b0 = (const float*)d_in[4];
    const float* W1 = (const float*)d_in[5];
    const float* b1 = (const float*)d_in[6];
    const float* W2 = (const float*)d_in[7];
    const float* b2 = (const float*)d_in[8];
    float* out = (float*)d_out;

    void *pX, *pAGG, *pns, *pnd, *pcs, *pcd, *pincl, *pcur, *pesrc, *pbsum, *pvec;
    cudaGetSymbolAddress(&pX,    g_X);
    cudaGetSymbolAddress(&pAGG,  g_AGG);
    cudaGetSymbolAddress(&pns,   g_ns);
    cudaGetSymbolAddress(&pnd,   g_nd);
    cudaGetSymbolAddress(&pcs,   g_cnts);
    cudaGetSymbolAddress(&pcd,   g_cntd);
    cudaGetSymbolAddress(&pincl, g_incl);
    cudaGetSymbolAddress(&pcur,  g_cur);
    cudaGetSymbolAddress(&pesrc, g_esrc);
    cudaGetSymbolAddress(&pbsum, g_bsum);
    cudaGetSymbolAddress(&pvec,  g_vec);
    float* X    = (float*)pX;
    float* AGG  = (float*)pAGG;
    float* ns   = (float*)pns;
    float* nd   = (float*)pnd;
    int*   cs   = (int*)pcs;
    int*   cd   = (int*)pcd;
    int*   incl = (int*)pincl;
    int*   cur  = (int*)pcur;
    int*   esrc = (int*)pesrc;
    int*   bsum = (int*)pbsum;
    float* vec  = (float*)pvec;

    const int nScanBlocks = (NN + 1023) / 1024;   // 98

    // --- degrees, norms, CSR ---
    cudaMemsetAsync(cs, 0, NN * sizeof(int));
    cudaMemsetAsync(cd, 0, NN * sizeof(int));
    hist_kernel<<<(NE + 255) / 256, 256>>>(src, dst, cs, cd);
    norm_kernel<<<(NN + 255) / 256, 256>>>(cs, cd, ns, nd);
    scan1_kernel<<<nScanBlocks, 256>>>(cd, incl, bsum);
    scan2_kernel<<<1, 32>>>(bsum, nScanBlocks);
    scan3_kernel<<<(NN + 255) / 256, 256>>>(incl, bsum, cd, cur);
    fill_kernel<<<(NE + 255) / 256, 256>>>(src, dst, cur, esrc);

    const int gatherBlocks = (NN * 32 + 255) / 256;   // one warp per node
    const int gemmBlocks   = (NN + 63) / 64;

    // --- layer 0 ---
    gather_kernel<0><<<gatherBlocks, 256>>>(h, ns, nd, incl, cd, esrc, AGG);
    gemm_kernel<<<gemmBlocks, 256>>>(AGG, W0, b0, X);

    // --- layer 1 ---
    gather_kernel<0><<<gatherBlocks, 256>>>(X, ns, nd, incl, cd, esrc, AGG);
    gemm_kernel<<<gemmBlocks, 256>>>(AGG, W1, b1, X);

    // --- layer 2: gather fused with column reduction, then micro-GEMM ---
    cudaMemsetAsync(vec, 0, DD * sizeof(float));
    gather_kernel<1><<<592, 256>>>(X, ns, nd, incl, cd, esrc, vec);
    final_kernel<<<1, DD>>>(W2, b2, vec, out);

    (void)in_sizes; (void)n_in; (void)out_size;
}

// round 4
// speedup vs baseline: 2.4278x; 1.5967x over previous
#include <cuda_runtime.h>
#include <cuda_fp16.h>
#include <cstdint>

#define NN 100000
#define NN_PAD 100096          // padded to multiple of 128 (GEMM tile)
#define NE 1600000
#define DD 128

// ------------------------- scratch (device globals) ------------------------
__device__ __half g_X  [(size_t)NN_PAD * DD];  // ns-prescaled features (fp16)
__device__ float  g_AGG[(size_t)NN_PAD * DD];  // aggregated features (fp32)
__device__ float  g_ns  [NN_PAD];              // norm_src (pad rows stay 0)
__device__ float  g_nd  [NN];
__device__ int    g_cnts[NN];
__device__ int    g_cntd[NN];
__device__ int    g_incl[NN];
__device__ int    g_cur [NN];
__device__ int    g_esrc[NE];
__device__ int    g_bsum[128];
__device__ float  g_vec [DD];

// ------------------------- histogram ---------------------------------------
__global__ void hist_kernel(const int* __restrict__ src,
                            const int* __restrict__ dst,
                            int* __restrict__ cs, int* __restrict__ cd) {
    int i = blockIdx.x * blockDim.x + threadIdx.x;
    if (i < NE) {
        atomicAdd(&cs[src[i]], 1);
        atomicAdd(&cd[dst[i]], 1);
    }
}

__global__ void norm_kernel(const int* __restrict__ cs, const int* __restrict__ cd,
                            float* __restrict__ ns, float* __restrict__ nd) {
    int i = blockIdx.x * blockDim.x + threadIdx.x;
    if (i < NN) {
        ns[i] = rsqrtf(fmaxf((float)cs[i], 1.0f));
        nd[i] = rsqrtf(fmaxf((float)cd[i], 1.0f));
    }
}

// ------------------------- scan (chunk=1024) -------------------------------
__global__ void scan1_kernel(const int* __restrict__ cnt,
                             int* __restrict__ incl, int* __restrict__ bsum) {
    __shared__ int s[256];
    int b = blockIdx.x, t = threadIdx.x;
    int base = b * 1024 + t * 4;
    int v0 = (base + 0 < NN) ? cnt[base + 0] : 0;
    int v1 = (base + 1 < NN) ? cnt[base + 1] : 0;
    int v2 = (base + 2 < NN) ? cnt[base + 2] : 0;
    int v3 = (base + 3 < NN) ? cnt[base + 3] : 0;
    int l1 = v0 + v1, l2 = l1 + v2, l3 = l2 + v3;
    s[t] = l3;
    __syncthreads();
    for (int off = 1; off < 256; off <<= 1) {
        int x = (t >= off) ? s[t - off] : 0;
        __syncthreads();
        s[t] += x;
        __syncthreads();
    }
    int prev = t ? s[t - 1] : 0;
    if (base + 0 < NN) incl[base + 0] = prev + v0;
    if (base + 1 < NN) incl[base + 1] = prev + l1;
    if (base + 2 < NN) incl[base + 2] = prev + l2;
    if (base + 3 < NN) incl[base + 3] = prev + l3;
    if (t == 255) bsum[b] = s[255];
}

__global__ void scan2_kernel(int* __restrict__ bsum, int nb) {
    __shared__ int s[128];
    int t = threadIdx.x;
    int v = (t < nb) ? bsum[t] : 0;
    s[t] = v;
    __syncthreads();
    for (int off = 1; off < 128; off <<= 1) {
        int x = (t >= off) ? s[t - off] : 0;
        __syncthreads();
        s[t] += x;
        __syncthreads();
    }
    if (t < nb) bsum[t] = s[t] - v;   // exclusive
}

__global__ void scan3_kernel(int* __restrict__ incl, const int* __restrict__ bsum,
                             const int* __restrict__ cnt, int* __restrict__ cur) {
    int i = blockIdx.x * blockDim.x + threadIdx.x;
    if (i < NN) {
        int v = incl[i] + bsum[i >> 10];
        incl[i] = v;
        cur[i]  = v - cnt[i];
    }
}

__global__ void fill_kernel(const int* __restrict__ src, const int* __restrict__ dst,
                            int* __restrict__ cur, int* __restrict__ esrc) {
    int i = blockIdx.x * blockDim.x + threadIdx.x;
    if (i < NE) {
        int pos = atomicAdd(&cur[dst[i]], 1);
        esrc[pos] = src[i];
    }
}

// ------------------------- h -> fp16, prescaled by ns ----------------------
__global__ void conv_kernel(const float* __restrict__ h,
                            const float* __restrict__ ns,
                            __half* __restrict__ X) {
    int i = blockIdx.x * blockDim.x + threadIdx.x;   // float4 index
    if (i < NN * DD / 4) {
        int row = i >> 5;
        float s = ns[row];
        float4 v = ((const float4*)h)[i];
        __half2 a = __floats2half2_rn(v.x * s, v.y * s);
        __half2 b = __floats2half2_rn(v.z * s, v.w * s);
        uint2 u;
        u.x = *(uint32_t*)&a;
        u.y = *(uint32_t*)&b;
        ((uint2*)X)[i] = u;
    }
}

// ------------------------- gather SpMM (fp16 in, fp32 acc) -----------------
// X already contains ns[src]*feat. acc = sum X[src]; out = acc * nd[d].
// MODE 0: store fp32 AGG.  MODE 1: accumulate column sums into vec.
template <int MODE>
__global__ void gather_kernel(const __half* __restrict__ Xh,
                              const float* __restrict__ nd,
                              const int* __restrict__ incl,
                              const int* __restrict__ cnt,
                              const int* __restrict__ esrc,
                              float* __restrict__ outp) {
    const int lane  = threadIdx.x & 31;
    const int warp0 = (blockIdx.x * blockDim.x + threadIdx.x) >> 5;
    const int nwarp = (gridDim.x * blockDim.x) >> 5;
    const uint2* __restrict__ Xv = (const uint2*)Xh;   // 32 x uint2 per row

    float4 tot = make_float4(0.f, 0.f, 0.f, 0.f);

    for (int node = warp0; node < NN; node += nwarp) {
        int end = incl[node];
        int beg = end - cnt[node];
        float4 acc = make_float4(0.f, 0.f, 0.f, 0.f);
        int e = beg;
        for (; e + 4 <= end; e += 4) {
            int s0 = esrc[e], s1 = esrc[e + 1], s2 = esrc[e + 2], s3 = esrc[e + 3];
            uint2 u0 = Xv[(size_t)s0 * 32 + lane];
            uint2 u1 = Xv[(size_t)s1 * 32 + lane];
            uint2 u2 = Xv[(size_t)s2 * 32 + lane];
            uint2 u3 = Xv[(size_t)s3 * 32 + lane];
#define ACC_U2(u) { \
            float2 f0 = __half22float2(*(__half2*)&u.x); \
            float2 f1 = __half22float2(*(__half2*)&u.y); \
            acc.x += f0.x; acc.y += f0.y; acc.z += f1.x; acc.w += f1.y; }
            ACC_U2(u0) ACC_U2(u1) ACC_U2(u2) ACC_U2(u3)
        }
        for (; e < end; e++) {
            int s = esrc[e];
            uint2 u = Xv[(size_t)s * 32 + lane];
            ACC_U2(u)
        }
#undef ACC_U2
        float sd = nd[node];
        acc.x *= sd; acc.y *= sd; acc.z *= sd; acc.w *= sd;
        if (MODE == 0) {
            ((float4*)outp)[(size_t)node * 32 + lane] = acc;
        } else {
            tot.x += acc.x; tot.y += acc.y; tot.z += acc.z; tot.w += acc.w;
        }
    }
    if (MODE == 1) {
        float* vp = outp + lane * 4;
        atomicAdd(vp + 0, tot.x);
        atomicAdd(vp + 1, tot.y);
        atomicAdd(vp + 2, tot.z);
        atomicAdd(vp + 3, tot.w);
    }
}

// ------------------------- tf32 tensor-core GEMM ---------------------------
// X[r,:] = half( relu(AGG[r,:] @ W + b) * ns[r] )
// BM=128, BN=128(=DD), BK=32; 8 warps (4 along M x 2 along N), warp tile 32x64.
__device__ __forceinline__ uint32_t f2tf(float x) {
    uint32_t r;
    asm("cvt.rna.tf32.f32 %0, %1;" : "=r"(r) : "f"(x));
    return r;
}
__device__ __forceinline__ void mma_tf32(float* d, const uint32_t* a, const uint32_t* b) {
    asm volatile("mma.sync.aligned.m16n8k8.row.col.f32.tf32.tf32.f32 "
                 "{%0,%1,%2,%3}, {%4,%5,%6,%7}, {%8,%9}, {%0,%1,%2,%3};"
                 : "+f"(d[0]), "+f"(d[1]), "+f"(d[2]), "+f"(d[3])
                 : "r"(a[0]), "r"(a[1]), "r"(a[2]), "r"(a[3]),
                   "r"(b[0]), "r"(b[1]));
}

__global__ __launch_bounds__(256, 2)
void gemm_tf32_kernel(const float* __restrict__ A, const float* __restrict__ W,
                      const float* __restrict__ bias, const float* __restrict__ ns,
                      __half* __restrict__ Out) {
    __shared__ uint32_t As[128][36];       // [m][k], pad -> conflict-free frag LDS
    __shared__ uint32_t Ws[32][132];       // [k][n]

    const int t    = threadIdx.x;
    const int lane = t & 31;
    const int warp = t >> 5;
    const int wm   = (warp & 3) * 32;      // warp M offset
    const int wn   = (warp >> 2) * 64;     // warp N offset
    const int row0 = blockIdx.x * 128;

    float acc[2][8][4];
#pragma unroll
    for (int m = 0; m < 2; m++)
#pragma unroll
        for (int f = 0; f < 8; f++)
#pragma unroll
            for (int i = 0; i < 4; i++) acc[m][f][i] = 0.0f;

    for (int kt = 0; kt < 4; kt++) {
        // A tile: 128x32 fp32 -> tf32 smem
#pragma unroll
        for (int j = 0; j < 4; j++) {
            int id = t + j * 256;
            int r  = id >> 3;
            int c4 = (id & 7) * 4;
            float4 v = *(const float4*)(A + (size_t)(row0 + r) * DD + kt * 32 + c4);
            As[r][c4 + 0] = f2tf(v.x);
            As[r][c4 + 1] = f2tf(v.y);
            As[r][c4 + 2] = f2tf(v.z);
            As[r][c4 + 3] = f2tf(v.w);
        }
        // W tile: 32x128 fp32 -> tf32 smem
#pragma unroll
        for (int j = 0; j < 4; j++) {
            int id = t + j * 256;
            int r  = id >> 5;
            int c4 = (id & 31) * 4;
            float4 v = *(const float4*)(W + (size_t)(kt * 32 + r) * DD + c4);
            Ws[r][c4 + 0] = f2tf(v.x);
            Ws[r][c4 + 1] = f2tf(v.y);
            Ws[r][c4 + 2] = f2tf(v.z);
            Ws[r][c4 + 3] = f2tf(v.w);
        }
        __syncthreads();

#pragma unroll
        for (int k8 = 0; k8 < 4; k8++) {
            const int kb = k8 * 8;
            const int ar = wm + (lane >> 2);
            const int ac = kb + (lane & 3);
            uint32_t a[2][4];
#pragma unroll
            for (int m = 0; m < 2; m++) {
                int r = ar + m * 16;
                a[m][0] = As[r][ac];
                a[m][1] = As[r + 8][ac];
                a[m][2] = As[r][ac + 4];
                a[m][3] = As[r + 8][ac + 4];
            }
            const int bk = kb + (lane & 3);
            const int bn = wn + (lane >> 2);
            uint32_t b[8][2];
#pragma unroll
            for (int f = 0; f < 8; f++) {
                b[f][0] = Ws[bk][bn + f * 8];
                b[f][1] = Ws[bk + 4][bn + f * 8];
            }
#pragma unroll
            for (int m = 0; m < 2; m++)
#pragma unroll
                for (int f = 0; f < 8; f++)
                    mma_tf32(acc[m][f], a[m], b[f]);
        }
        __syncthreads();
    }

    // epilogue: bias + relu, * ns[row], convert fp16, store half2 pairs
#pragma unroll
    for (int m = 0; m < 2; m++) {
        int ra = row0 + wm + m * 16 + (lane >> 2);
        int rb = ra + 8;
        float sa = ns[ra];
        float sb = ns[rb];
#pragma unroll
        for (int f = 0; f < 8; f++) {
            int n  = wn + f * 8 + (lane & 3) * 2;
            float b0 = __ldg(bias + n);
            float b1 = __ldg(bias + n + 1);
            float v0 = fmaxf(acc[m][f][0] + b0, 0.0f) * sa;
            float v1 = fmaxf(acc[m][f][1] + b1, 0.0f) * sa;
            float v2 = fmaxf(acc[m][f][2] + b0, 0.0f) * sb;
            float v3 = fmaxf(acc[m][f][3] + b1, 0.0f) * sb;
            *(__half2*)(Out + (size_t)ra * DD + n) = __floats2half2_rn(v0, v1);
            *(__half2*)(Out + (size_t)rb * DD + n) = __floats2half2_rn(v2, v3);
        }
    }
}

// ------------------------- final micro-GEMM: out = (vec/N) @ W2 + b2 -------
__global__ void final_kernel(const float* __restrict__ W2,
                             const float* __restrict__ b2,
                             const float* __restrict__ vec,
                             float* __restrict__ out) {
    __shared__ float v[DD];
    int c = threadIdx.x;
    v[c] = vec[c] * (1.0f / (float)NN);
    __syncthreads();
    float acc = b2[c];
#pragma unroll 8
    for (int k = 0; k < DD; k++)
        acc = fmaf(v[k], W2[(size_t)k * DD + c], acc);
    out[c] = acc;
}

// ===========================================================================
extern "C" void kernel_launch(void* const* d_in, const int* in_sizes, int n_in,
                              void* d_out, int out_size) {
    const float* h   = (const float*)d_in[0];
    const int*   src = (const int*)d_in[1];   // JAX demotes int64 -> int32
    const int*   dst = (const int*)d_in[2];
    const float* W0 = (const float*)d_in[3];
    const float* b0 = (const float*)d_in[4];
    const float* W1 = (const float*)d_in[5];
    const float* b1 = (const float*)d_in[6];
    const float* W2 = (const float*)d_in[7];
    const float* b2 = (const float*)d_in[8];
    float* out = (float*)d_out;

    void *pX, *pAGG, *pns, *pnd, *pcs, *pcd, *pincl, *pcur, *pesrc, *pbsum, *pvec;
    cudaGetSymbolAddress(&pX,    g_X);
    cudaGetSymbolAddress(&pAGG,  g_AGG);
    cudaGetSymbolAddress(&pns,   g_ns);
    cudaGetSymbolAddress(&pnd,   g_nd);
    cudaGetSymbolAddress(&pcs,   g_cnts);
    cudaGetSymbolAddress(&pcd,   g_cntd);
    cudaGetSymbolAddress(&pincl, g_incl);
    cudaGetSymbolAddress(&pcur,  g_cur);
    cudaGetSymbolAddress(&pesrc, g_esrc);
    cudaGetSymbolAddress(&pbsum, g_bsum);
    cudaGetSymbolAddress(&pvec,  g_vec);
    __half* X   = (__half*)pX;
    float* AGG  = (float*)pAGG;
    float* ns   = (float*)pns;
    float* nd   = (float*)pnd;
    int*   cs   = (int*)pcs;
    int*   cd   = (int*)pcd;
    int*   incl = (int*)pincl;
    int*   cur  = (int*)pcur;
    int*   esrc = (int*)pesrc;
    int*   bsum = (int*)pbsum;
    float* vec  = (float*)pvec;

    const int nScanBlocks = (NN + 1023) / 1024;   // 98

    // --- degrees, norms, CSR-by-dst ---
    cudaMemsetAsync(cs, 0, NN * sizeof(int));
    cudaMemsetAsync(cd, 0, NN * sizeof(int));
    hist_kernel<<<(NE + 255) / 256, 256>>>(src, dst, cs, cd);
    norm_kernel<<<(NN + 255) / 256, 256>>>(cs, cd, ns, nd);
    scan1_kernel<<<nScanBlocks, 256>>>(cd, incl, bsum);
    scan2_kernel<<<1, 128>>>(bsum, nScanBlocks);
    scan3_kernel<<<(NN + 255) / 256, 256>>>(incl, bsum, cd, cur);
    fill_kernel<<<(NE + 255) / 256, 256>>>(src, dst, cur, esrc);

    // --- X0 = half(h * ns) ---
    conv_kernel<<<(NN * DD / 4 + 255) / 256, 256>>>(h, ns, X);

    const int gatherBlocks = (NN * 32 + 255) / 256;
    const int gemmBlocks   = NN_PAD / 128;

    // --- layer 0 ---
    gather_kernel<0><<<gatherBlocks, 256>>>(X, nd, incl, cd, esrc, AGG);
    gemm_tf32_kernel<<<gemmBlocks, 256>>>(AGG, W0, b0, ns, X);

    // --- layer 1 ---
    gather_kernel<0><<<gatherBlocks, 256>>>(X, nd, incl, cd, esrc, AGG);
    gemm_tf32_kernel<<<gemmBlocks, 256>>>(AGG, W1, b1, ns, X);

    // --- layer 2: gather fused with column reduction, then micro-GEMM ---
    cudaMemsetAsync(vec, 0, DD * sizeof(float));
    gather_kernel<1><<<592, 256>>>(X, nd, incl, cd, esrc, vec);
    final_kernel<<<1, DD>>>(W2, b2, vec, out);

    (void)in_sizes; (void)n_in; (void)out_size;
}

// round 5
// speedup vs baseline: 2.5372x; 1.0451x over previous
#include <cuda_runtime.h>
#include <cuda_fp16.h>
#include <cstdint>

#define NN 100000
#define NN_PAD 100096          // multiple of 128
#define NE 1600000
#define DD 128

// ------------------------- scratch (device globals) ------------------------
__device__ __half g_X [(size_t)NN_PAD * DD];   // fp16 features (ping)
__device__ __half g_Y [(size_t)NN_PAD * DD];   // fp16 features (pong)
__device__ float  g_ns  [NN_PAD];              // norm_src (pad rows stay 0)
__device__ float  g_nd  [NN];
__device__ float  g_c   [NN];                  // layer-2 fold coefficients
__device__ int    g_cnts[NN];
__device__ int    g_cntd[NN];
__device__ int    g_incl[NN];
__device__ int    g_cur [NN];
__device__ int    g_esrc[NE];
__device__ int    g_bsum[128];
__device__ float  g_vec [DD];
__device__ __half g_Wt0[DD * DD];              // W0^T fp16 [n][k]
__device__ __half g_Wt1[DD * DD];              // W1^T fp16 [n][k]

// ------------------------- histogram ---------------------------------------
__global__ void hist_kernel(const int* __restrict__ src,
                            const int* __restrict__ dst,
                            int* __restrict__ cs, int* __restrict__ cd) {
    int i = blockIdx.x * blockDim.x + threadIdx.x;
    if (i < NE) {
        atomicAdd(&cs[src[i]], 1);
        atomicAdd(&cd[dst[i]], 1);
    }
}

__global__ void norm_kernel(const int* __restrict__ cs, const int* __restrict__ cd,
                            float* __restrict__ ns, float* __restrict__ nd) {
    int i = blockIdx.x * blockDim.x + threadIdx.x;
    if (i < NN) {
        ns[i] = rsqrtf(fmaxf((float)cs[i], 1.0f));
        nd[i] = rsqrtf(fmaxf((float)cd[i], 1.0f));
    }
}

// ------------------------- scan (chunk=1024) -------------------------------
__global__ void scan1_kernel(const int* __restrict__ cnt,
                             int* __restrict__ incl, int* __restrict__ bsum) {
    __shared__ int s[256];
    int b = blockIdx.x, t = threadIdx.x;
    int base = b * 1024 + t * 4;
    int v0 = (base + 0 < NN) ? cnt[base + 0] : 0;
    int v1 = (base + 1 < NN) ? cnt[base + 1] : 0;
    int v2 = (base + 2 < NN) ? cnt[base + 2] : 0;
    int v3 = (base + 3 < NN) ? cnt[base + 3] : 0;
    int l1 = v0 + v1, l2 = l1 + v2, l3 = l2 + v3;
    s[t] = l3;
    __syncthreads();
    for (int off = 1; off < 256; off <<= 1) {
        int x = (t >= off) ? s[t - off] : 0;
        __syncthreads();
        s[t] += x;
        __syncthreads();
    }
    int prev = t ? s[t - 1] : 0;
    if (base + 0 < NN) incl[base + 0] = prev + v0;
    if (base + 1 < NN) incl[base + 1] = prev + l1;
    if (base + 2 < NN) incl[base + 2] = prev + l2;
    if (base + 3 < NN) incl[base + 3] = prev + l3;
    if (t == 255) bsum[b] = s[255];
}

__global__ void scan2_kernel(int* __restrict__ bsum, int nb) {
    __shared__ int s[128];
    int t = threadIdx.x;
    int v = (t < nb) ? bsum[t] : 0;
    s[t] = v;
    __syncthreads();
    for (int off = 1; off < 128; off <<= 1) {
        int x = (t >= off) ? s[t - off] : 0;
        __syncthreads();
        s[t] += x;
        __syncthreads();
    }
    if (t < nb) bsum[t] = s[t] - v;   // exclusive
}

__global__ void scan3_kernel(int* __restrict__ incl, const int* __restrict__ bsum,
                             const int* __restrict__ cnt, int* __restrict__ cur) {
    int i = blockIdx.x * blockDim.x + threadIdx.x;
    if (i < NN) {
        int v = incl[i] + bsum[i >> 10];
        incl[i] = v;
        cur[i]  = v - cnt[i];
    }
}

// CSR fill + layer-2 fold coefficient c[src] += nd[dst]
__global__ void fill_kernel(const int* __restrict__ src, const int* __restrict__ dst,
                            const float* __restrict__ nd,
                            int* __restrict__ cur, int* __restrict__ esrc,
                            float* __restrict__ c) {
    int i = blockIdx.x * blockDim.x + threadIdx.x;
    if (i < NE) {
        int s = src[i], d = dst[i];
        int pos = atomicAdd(&cur[d], 1);
        esrc[pos] = s;
        atomicAdd(&c[s], nd[d]);
    }
}

// ------------------------- h -> fp16, prescaled by ns ----------------------
__global__ void conv_kernel(const float* __restrict__ h,
                            const float* __restrict__ ns,
                            __half* __restrict__ X) {
    int i = blockIdx.x * blockDim.x + threadIdx.x;   // float4 index
    if (i < NN * DD / 4) {
        int row = i >> 5;
        float s = ns[row];
        float4 v = ((const float4*)h)[i];
        __half2 a = __floats2half2_rn(v.x * s, v.y * s);
        __half2 b = __floats2half2_rn(v.z * s, v.w * s);
        uint2 u;
        u.x = *(uint32_t*)&a;
        u.y = *(uint32_t*)&b;
        ((uint2*)X)[i] = u;
    }
}

// ------------------------- W -> W^T fp16 -----------------------------------
__global__ void prep_kernel(const float* __restrict__ W, __half* __restrict__ Wt) {
    int i = blockIdx.x * blockDim.x + threadIdx.x;
    if (i < DD * DD) {
        int k = i >> 7, n = i & 127;
        Wt[n * DD + k] = __float2half(W[i]);
    }
}

// ------------------------- fused gather + fp16 MMA GEMM --------------------
// Per block: 128 dst rows. Phase A: gather+nd-scale into smem As (fp16).
// Phase B: X_out[r,:] = half( relu(As[r,:] @ W + b) * ns[r] ).
// Wt: fp16 [n][k]. Dynamic smem: As[128][136] + Wsh[128][136] halves.
#define SPAD 136
__device__ __forceinline__ void mma_f16(float* d, const uint32_t* a, const uint32_t* b) {
    asm volatile("mma.sync.aligned.m16n8k16.row.col.f32.f16.f16.f32 "
                 "{%0,%1,%2,%3}, {%4,%5,%6,%7}, {%8,%9}, {%0,%1,%2,%3};"
                 : "+f"(d[0]), "+f"(d[1]), "+f"(d[2]), "+f"(d[3])
                 : "r"(a[0]), "r"(a[1]), "r"(a[2]), "r"(a[3]),
                   "r"(b[0]), "r"(b[1]));
}

__global__ __launch_bounds__(256)
void fused_kernel(const __half* __restrict__ Xin,
                  const float* __restrict__ nd, const float* __restrict__ ns,
                  const int* __restrict__ incl, const int* __restrict__ cnt,
                  const int* __restrict__ esrc,
                  const __half* __restrict__ Wt, const float* __restrict__ bias,
                  __half* __restrict__ Out) {
    extern __shared__ __half smem[];
    __half (*As)[SPAD]  = (__half(*)[SPAD])smem;
    __half (*Wsh)[SPAD] = (__half(*)[SPAD])(smem + 128 * SPAD);

    const int t    = threadIdx.x;
    const int lane = t & 31;
    const int warp = t >> 5;
    const int row0 = blockIdx.x * 128;
    const uint2* __restrict__ Xv = (const uint2*)Xin;

    // ---- copy Wt into smem (16B chunks) ----
#pragma unroll
    for (int j = 0; j < 8; j++) {
        int id = t + j * 256;           // 0..2047 uint4
        int n  = id >> 4;
        int kq = id & 15;
        *(uint4*)&Wsh[n][kq * 8] = *(const uint4*)(Wt + (size_t)n * DD + kq * 8);
    }

    // ---- Phase A: gather 16 nodes per warp ----
    for (int i = 0; i < 16; i++) {
        int r    = warp * 16 + i;
        int node = row0 + r;
        float4 acc = make_float4(0.f, 0.f, 0.f, 0.f);
        if (node < NN) {
            int end = incl[node];
            int e   = end - cnt[node];
            for (; e + 4 <= end; e += 4) {
                int s0 = esrc[e], s1 = esrc[e + 1], s2 = esrc[e + 2], s3 = esrc[e + 3];
                uint2 u0 = Xv[(size_t)s0 * 32 + lane];
                uint2 u1 = Xv[(size_t)s1 * 32 + lane];
                uint2 u2 = Xv[(size_t)s2 * 32 + lane];
                uint2 u3 = Xv[(size_t)s3 * 32 + lane];
#define ACC_U2(u) { \
                float2 f0 = __half22float2(*(__half2*)&u.x); \
                float2 f1 = __half22float2(*(__half2*)&u.y); \
                acc.x += f0.x; acc.y += f0.y; acc.z += f1.x; acc.w += f1.y; }
                ACC_U2(u0) ACC_U2(u1) ACC_U2(u2) ACC_U2(u3)
            }
            for (; e < end; e++) {
                int s = esrc[e];
                uint2 u = Xv[(size_t)s * 32 + lane];
                ACC_U2(u)
            }
#undef ACC_U2
            float sd = nd[node];
            acc.x *= sd; acc.y *= sd; acc.z *= sd; acc.w *= sd;
        }
        __half2 h0 = __floats2half2_rn(acc.x, acc.y);
        __half2 h1 = __floats2half2_rn(acc.z, acc.w);
        uint2 u;
        u.x = *(uint32_t*)&h0;
        u.y = *(uint32_t*)&h1;
        *(uint2*)&As[r][lane * 4] = u;
    }
    __syncthreads();

    // ---- Phase B: 128x128x128 fp16 MMA ----
    const int wm = (warp & 3) * 32;
    const int wn = (warp >> 2) * 64;

    float acc[2][8][4];
#pragma unroll
    for (int m = 0; m < 2; m++)
#pragma unroll
        for (int f = 0; f < 8; f++)
#pragma unroll
            for (int i = 0; i < 4; i++) acc[m][f][i] = 0.0f;

    const int g  = lane >> 2;       // group 0..7
    const int tg = (lane & 3) * 2;  // 0,2,4,6

#pragma unroll
    for (int ks = 0; ks < 8; ks++) {
        const int k0 = ks * 16;
        uint32_t a[2][4];
#pragma unroll
        for (int m = 0; m < 2; m++) {
            int r = wm + m * 16 + g;
            a[m][0] = *(const uint32_t*)&As[r][k0 + tg];
            a[m][1] = *(const uint32_t*)&As[r + 8][k0 + tg];
            a[m][2] = *(const uint32_t*)&As[r][k0 + tg + 8];
            a[m][3] = *(const uint32_t*)&As[r + 8][k0 + tg + 8];
        }
        uint32_t b[8][2];
#pragma unroll
        for (int f = 0; f < 8; f++) {
            int n = wn + f * 8 + g;
            b[f][0] = *(const uint32_t*)&Wsh[n][k0 + tg];
            b[f][1] = *(const uint32_t*)&Wsh[n][k0 + tg + 8];
        }
#pragma unroll
        for (int m = 0; m < 2; m++)
#pragma unroll
            for (int f = 0; f < 8; f++)
                mma_f16(acc[m][f], a[m], b[f]);
    }

    // ---- epilogue: bias + relu, * ns, fp16 store ----
#pragma unroll
    for (int m = 0; m < 2; m++) {
        int ra = row0 + wm + m * 16 + g;
        int rb = ra + 8;
        float sa = ns[ra];
        float sb = ns[rb];
#pragma unroll
        for (int f = 0; f < 8; f++) {
            int n  = wn + f * 8 + tg;
            float b0 = __ldg(bias + n);
            float b1 = __ldg(bias + n + 1);
            float v0 = fmaxf(acc[m][f][0] + b0, 0.0f) * sa;
            float v1 = fmaxf(acc[m][f][1] + b1, 0.0f) * sa;
            float v2 = fmaxf(acc[m][f][2] + b0, 0.0f) * sb;
            float v3 = fmaxf(acc[m][f][3] + b1, 0.0f) * sb;
            *(__half2*)(Out + (size_t)ra * DD + n) = __floats2half2_rn(v0, v1);
            *(__half2*)(Out + (size_t)rb * DD + n) = __floats2half2_rn(v2, v3);
        }
    }
}

// ------------------------- layer-2 folded reduce ---------------------------
// vec[c] = sum_s cs[s] * X[s][c]
#define WR_ROWS 784
__global__ void wreduce_kernel(const __half* __restrict__ X,
                               const float* __restrict__ cf,
                               float* __restrict__ vec) {
    __shared__ float sm[256];
    int col = threadIdx.x & 127;
    int ph  = threadIdx.x >> 7;
    int r0  = blockIdx.x * WR_ROWS;
    int rend = min(r0 + WR_ROWS, NN);
    float s = 0.0f;
    for (int r = r0 + ph; r < rend; r += 2)
        s = fmaf(cf[r], __half2float(X[(size_t)r * DD + col]), s);
    sm[threadIdx.x] = s;
    __syncthreads();
    if (ph == 0)
        atomicAdd(&vec[col], sm[col] + sm[col + 128]);
}

// ------------------------- final micro-GEMM: out = (vec/N) @ W2 + b2 -------
__global__ void final_kernel(const float* __restrict__ W2,
                             const float* __restrict__ b2,
                             const float* __restrict__ vec,
                             float* __restrict__ out) {
    __shared__ float v[DD];
    int c = threadIdx.x;
    v[c] = vec[c] * (1.0f / (float)NN);
    __syncthreads();
    float acc = b2[c];
#pragma unroll 8
    for (int k = 0; k < DD; k++)
        acc = fmaf(v[k], W2[(size_t)k * DD + c], acc);
    out[c] = acc;
}

// ===========================================================================
extern "C" void kernel_launch(void* const* d_in, const int* in_sizes, int n_in,
                              void* d_out, int out_size) {
    const float* h   = (const float*)d_in[0];
    const int*   src = (const int*)d_in[1];   // JAX demotes int64 -> int32
    const int*   dst = (const int*)d_in[2];
    const float* W0 = (const float*)d_in[3];
    const float* b0 = (const float*)d_in[4];
    const float* W1 = (const float*)d_in[5];
    const float* b1 = (const float*)d_in[6];
    const float* W2 = (const float*)d_in[7];
    const float* b2 = (const float*)d_in[8];
    float* out = (float*)d_out;

    void *pX, *pY, *pns, *pnd, *pc, *pcs, *pcd, *pincl, *pcur, *pesrc, *pbsum,
         *pvec, *pWt0, *pWt1;
    cudaGetSymbolAddress(&pX,    g_X);
    cudaGetSymbolAddress(&pY,    g_Y);
    cudaGetSymbolAddress(&pns,   g_ns);
    cudaGetSymbolAddress(&pnd,   g_nd);
    cudaGetSymbolAddress(&pc,    g_c);
    cudaGetSymbolAddress(&pcs,   g_cnts);
    cudaGetSymbolAddress(&pcd,   g_cntd);
    cudaGetSymbolAddress(&pincl, g_incl);
    cudaGetSymbolAddress(&pcur,  g_cur);
    cudaGetSymbolAddress(&pesrc, g_esrc);
    cudaGetSymbolAddress(&pbsum, g_bsum);
    cudaGetSymbolAddress(&pvec,  g_vec);
    cudaGetSymbolAddress(&pWt0,  g_Wt0);
    cudaGetSymbolAddress(&pWt1,  g_Wt1);
    __half* X   = (__half*)pX;
    __half* Y   = (__half*)pY;
    float* ns   = (float*)pns;
    float* nd   = (float*)pnd;
    float* cf   = (float*)pc;
    int*   cs   = (int*)pcs;
    int*   cd   = (int*)pcd;
    int*   incl = (int*)pincl;
    int*   cur  = (int*)pcur;
    int*   esrc = (int*)pesrc;
    int*   bsum = (int*)pbsum;
    float* vec  = (float*)pvec;
    __half* Wt0 = (__half*)pWt0;
    __half* Wt1 = (__half*)pWt1;

    static int smemSet = 0;
    const int fusedSmem = 2 * 128 * SPAD * sizeof(__half);   // 69632 B
    if (!smemSet) {
        cudaFuncSetAttribute(fused_kernel,
                             cudaFuncAttributeMaxDynamicSharedMemorySize, fusedSmem);
        smemSet = 1;
    }

    const int nScanBlocks = (NN + 1023) / 1024;   // 98

    // --- degrees, norms, CSR-by-dst, fold coefficients ---
    cudaMemsetAsync(cs, 0, NN * sizeof(int));
    cudaMemsetAsync(cd, 0, NN * sizeof(int));
    cudaMemsetAsync(cf, 0, NN * sizeof(float));
    hist_kernel<<<(NE + 255) / 256, 256>>>(src, dst, cs, cd);
    norm_kernel<<<(NN + 255) / 256, 256>>>(cs, cd, ns, nd);
    scan1_kernel<<<nScanBlocks, 256>>>(cd, incl, bsum);
    scan2_kernel<<<1, 128>>>(bsum, nScanBlocks);
    scan3_kernel<<<(NN + 255) / 256, 256>>>(incl, bsum, cd, cur);
    fill_kernel<<<(NE + 255) / 256, 256>>>(src, dst, nd, cur, esrc, cf);

    // --- weight prep + X0 = half(h * ns) ---
    prep_kernel<<<64, 256>>>(W0, Wt0);
    prep_kernel<<<64, 256>>>(W1, Wt1);
    conv_kernel<<<(NN * DD / 4 + 255) / 256, 256>>>(h, ns, X);

    const int fusedBlocks = NN_PAD / 128;   // 782

    // --- layer 0: X -> Y ---
    fused_kernel<<<fusedBlocks, 256, fusedSmem>>>(X, nd, ns, incl, cd, esrc, Wt0, b0, Y);
    // --- layer 1: Y -> X ---
    fused_kernel<<<fusedBlocks, 256, fusedSmem>>>(Y, nd, ns, incl, cd, esrc, Wt1, b1, X);

    // --- layer 2 (folded): vec = sum_s c[s]*X[s]; out = (vec/N) @ W2 + b2 ---
    cudaMemsetAsync(vec, 0, DD * sizeof(float));
    wreduce_kernel<<<(NN + WR_ROWS - 1) / WR_ROWS, 256>>>(X, cf, vec);
    final_kernel<<<1, DD>>>(W2, b2, vec, out);

    (void)in_sizes; (void)n_in; (void)out_size;
}

// round 6
// speedup vs baseline: 3.8489x; 1.5170x over previous
#include <cuda_runtime.h>
#include <cuda_fp16.h>
#include <cstdint>

#define NN 100000
#define NN_PAD 100096          // multiple of 128
#define NE 1600000
#define DD 128
#define SPAD 136

// ------------------------- scratch (device globals) ------------------------
__device__ __half g_X  [(size_t)NN_PAD * DD];  // fp16 features (ping)
__device__ __half g_Y  [(size_t)NN_PAD * DD];  // fp16 features (pong)
__device__ __half g_AGG[(size_t)NN_PAD * DD];  // fp16 aggregated (pad rows stay 0)
__device__ float  g_ns  [NN_PAD];              // norm_src (pad rows stay 0)
__device__ float  g_nd  [NN];
__device__ float  g_c   [NN];                  // layer-2 fold coefficients
__device__ int    g_cnt2[2 * NN];              // [0,NN): src deg, [NN,2NN): dst deg
__device__ int    g_incl[NN];
__device__ int    g_cur [NN];
__device__ int    g_esrc[NE];
__device__ int    g_bsum[128];
__device__ float  g_vec [DD];
__device__ __half g_Wt0[DD * DD];              // W0^T fp16 [n][k]
__device__ __half g_Wt1[DD * DD];              // W1^T fp16 [n][k]

// ------------------------- histogram ---------------------------------------
__global__ void hist_kernel(const int* __restrict__ src,
                            const int* __restrict__ dst,
                            int* __restrict__ cnt2) {
    int i = blockIdx.x * blockDim.x + threadIdx.x;
    if (i < NE) {
        atomicAdd(&cnt2[src[i]], 1);
        atomicAdd(&cnt2[NN + dst[i]], 1);
    }
}

// ------------------------- scan (chunk=1024) -------------------------------
__global__ void scan1_kernel(const int* __restrict__ cnt,
                             int* __restrict__ incl, int* __restrict__ bsum) {
    __shared__ int s[256];
    int b = blockIdx.x, t = threadIdx.x;
    int base = b * 1024 + t * 4;
    int v0 = (base + 0 < NN) ? cnt[base + 0] : 0;
    int v1 = (base + 1 < NN) ? cnt[base + 1] : 0;
    int v2 = (base + 2 < NN) ? cnt[base + 2] : 0;
    int v3 = (base + 3 < NN) ? cnt[base + 3] : 0;
    int l1 = v0 + v1, l2 = l1 + v2, l3 = l2 + v3;
    s[t] = l3;
    __syncthreads();
    for (int off = 1; off < 256; off <<= 1) {
        int x = (t >= off) ? s[t - off] : 0;
        __syncthreads();
        s[t] += x;
        __syncthreads();
    }
    int prev = t ? s[t - 1] : 0;
    if (base + 0 < NN) incl[base + 0] = prev + v0;
    if (base + 1 < NN) incl[base + 1] = prev + l1;
    if (base + 2 < NN) incl[base + 2] = prev + l2;
    if (base + 3 < NN) incl[base + 3] = prev + l3;
    if (t == 255) bsum[b] = s[255];
}

__global__ void scan2_kernel(int* __restrict__ bsum, int nb) {
    __shared__ int s[128];
    int t = threadIdx.x;
    int v = (t < nb) ? bsum[t] : 0;
    s[t] = v;
    __syncthreads();
    for (int off = 1; off < 128; off <<= 1) {
        int x = (t >= off) ? s[t - off] : 0;
        __syncthreads();
        s[t] += x;
        __syncthreads();
    }
    if (t < nb) bsum[t] = s[t] - v;   // exclusive
}

// incl finalize + cursors + degree norms (norm fused in)
__global__ void scan3_kernel(int* __restrict__ incl, const int* __restrict__ bsum,
                             const int* __restrict__ cnt2,
                             int* __restrict__ cur,
                             float* __restrict__ ns, float* __restrict__ nd) {
    int i = blockIdx.x * blockDim.x + threadIdx.x;
    if (i < NN) {
        int cd = cnt2[NN + i];
        int v  = incl[i] + bsum[i >> 10];
        incl[i] = v;
        cur[i]  = v - cd;
        ns[i] = rsqrtf(fmaxf((float)cnt2[i], 1.0f));
        nd[i] = rsqrtf(fmaxf((float)cd, 1.0f));
    }
}

// CSR fill + layer-2 fold coefficient c[src] += nd[dst]
__global__ void fill_kernel(const int* __restrict__ src, const int* __restrict__ dst,
                            const float* __restrict__ nd,
                            int* __restrict__ cur, int* __restrict__ esrc,
                            float* __restrict__ c) {
    int i = blockIdx.x * blockDim.x + threadIdx.x;
    if (i < NE) {
        int s = src[i], d = dst[i];
        int pos = atomicAdd(&cur[d], 1);
        esrc[pos] = s;
        atomicAdd(&c[s], nd[d]);
    }
}

// ------------------------- h -> fp16 prescaled by ns -----------------------
__global__ void conv_kernel(const float* __restrict__ h,
                            const float* __restrict__ ns,
                            __half* __restrict__ X) {
    int i = blockIdx.x * blockDim.x + threadIdx.x;   // float4 index
    if (i < NN * DD / 4) {
        int row = i >> 5;
        float s = ns[row];
        float4 v = ((const float4*)h)[i];
        __half2 a = __floats2half2_rn(v.x * s, v.y * s);
        __half2 b = __floats2half2_rn(v.z * s, v.w * s);
        uint2 u;
        u.x = *(uint32_t*)&a;
        u.y = *(uint32_t*)&b;
        ((uint2*)X)[i] = u;
    }
}

// ------------------------- W0,W1 -> W^T fp16 -------------------------------
__global__ void prep_kernel(const float* __restrict__ W0, const float* __restrict__ W1,
                            __half* __restrict__ Wt0, __half* __restrict__ Wt1) {
    int i = blockIdx.x * blockDim.x + threadIdx.x;
    if (i < DD * DD) {
        int k = i >> 7, n = i & 127;
        Wt0[n * DD + k] = __float2half(W0[i]);
        Wt1[n * DD + k] = __float2half(W1[i]);
    }
}

// ------------------------- gather SpMM (fp16 in/out, fp32 acc) -------------
// AGG[d,:] = half( nd[d] * sum_{e->d} X[src_e,:] )   (X pre-scaled by ns)
__global__ void gather_kernel(const __half* __restrict__ Xh,
                              const float* __restrict__ nd,
                              const int* __restrict__ incl,
                              const int* __restrict__ cnt2,
                              const int* __restrict__ esrc,
                              __half* __restrict__ outp) {
    const int lane  = threadIdx.x & 31;
    const int warp0 = (blockIdx.x * blockDim.x + threadIdx.x) >> 5;
    const int nwarp = (gridDim.x * blockDim.x) >> 5;
    const uint2* __restrict__ Xv = (const uint2*)Xh;   // 32 x uint2 per row

    for (int node = warp0; node < NN; node += nwarp) {
        int end = incl[node];
        int beg = end - cnt2[NN + node];
        float4 acc = make_float4(0.f, 0.f, 0.f, 0.f);
        int e = beg;
        for (; e + 4 <= end; e += 4) {
            int s0 = esrc[e], s1 = esrc[e + 1], s2 = esrc[e + 2], s3 = esrc[e + 3];
            uint2 u0 = Xv[(size_t)s0 * 32 + lane];
            uint2 u1 = Xv[(size_t)s1 * 32 + lane];
            uint2 u2 = Xv[(size_t)s2 * 32 + lane];
            uint2 u3 = Xv[(size_t)s3 * 32 + lane];
#define ACC_U2(u) { \
            float2 f0 = __half22float2(*(__half2*)&u.x); \
            float2 f1 = __half22float2(*(__half2*)&u.y); \
            acc.x += f0.x; acc.y += f0.y; acc.z += f1.x; acc.w += f1.y; }
            ACC_U2(u0) ACC_U2(u1) ACC_U2(u2) ACC_U2(u3)
        }
        for (; e < end; e++) {
            int s = esrc[e];
            uint2 u = Xv[(size_t)s * 32 + lane];
            ACC_U2(u)
        }
#undef ACC_U2
        float sd = nd[node];
        __half2 h0 = __floats2half2_rn(acc.x * sd, acc.y * sd);
        __half2 h1 = __floats2half2_rn(acc.z * sd, acc.w * sd);
        uint2 u;
        u.x = *(uint32_t*)&h0;
        u.y = *(uint32_t*)&h1;
        ((uint2*)outp)[(size_t)node * 32 + lane] = u;
    }
}

// ------------------------- fp16 MMA GEMM -----------------------------------
// Out[r,:] = half( relu(AGG[r,:] @ W + b) * ns[r] );  Wt fp16 [n][k].
__device__ __forceinline__ void mma_f16(float* d, const uint32_t* a, const uint32_t* b) {
    asm volatile("mma.sync.aligned.m16n8k16.row.col.f32.f16.f16.f32 "
                 "{%0,%1,%2,%3}, {%4,%5,%6,%7}, {%8,%9}, {%0,%1,%2,%3};"
                 : "+f"(d[0]), "+f"(d[1]), "+f"(d[2]), "+f"(d[3])
                 : "r"(a[0]), "r"(a[1]), "r"(a[2]), "r"(a[3]),
                   "r"(b[0]), "r"(b[1]));
}

__global__ __launch_bounds__(256)
void gemm_f16_kernel(const __half* __restrict__ A,
                     const __half* __restrict__ Wt, const float* __restrict__ bias,
                     const float* __restrict__ ns, __half* __restrict__ Out) {
    extern __shared__ __half smem[];
    __half (*As)[SPAD]  = (__half(*)[SPAD])smem;
    __half (*Wsh)[SPAD] = (__half(*)[SPAD])(smem + 128 * SPAD);

    const int t    = threadIdx.x;
    const int lane = t & 31;
    const int warp = t >> 5;
    const int row0 = blockIdx.x * 128;

    // stage A tile (128x128 fp16) and W^T
#pragma unroll
    for (int j = 0; j < 8; j++) {
        int id = t + j * 256;           // 0..2047 uint4 (8 halves)
        int r  = id >> 4;
        int c8 = (id & 15) * 8;
        *(uint4*)&As[r][c8]  = *(const uint4*)(A  + (size_t)(row0 + r) * DD + c8);
        *(uint4*)&Wsh[r][c8] = *(const uint4*)(Wt + (size_t)r * DD + c8);
    }
    __syncthreads();

    const int wm = (warp & 3) * 32;
    const int wn = (warp >> 2) * 64;
    const int g  = lane >> 2;       // 0..7
    const int tg = (lane & 3) * 2;  // 0,2,4,6

    float acc[2][8][4];
#pragma unroll
    for (int m = 0; m < 2; m++)
#pragma unroll
        for (int f = 0; f < 8; f++)
#pragma unroll
            for (int i = 0; i < 4; i++) acc[m][f][i] = 0.0f;

#pragma unroll
    for (int ks = 0; ks < 8; ks++) {
        const int k0 = ks * 16;
        uint32_t a[2][4];
#pragma unroll
        for (int m = 0; m < 2; m++) {
            int r = wm + m * 16 + g;
            a[m][0] = *(const uint32_t*)&As[r][k0 + tg];
            a[m][1] = *(const uint32_t*)&As[r + 8][k0 + tg];
            a[m][2] = *(const uint32_t*)&As[r][k0 + tg + 8];
            a[m][3] = *(const uint32_t*)&As[r + 8][k0 + tg + 8];
        }
        uint32_t b[8][2];
#pragma unroll
        for (int f = 0; f < 8; f++) {
            int n = wn + f * 8 + g;
            b[f][0] = *(const uint32_t*)&Wsh[n][k0 + tg];
            b[f][1] = *(const uint32_t*)&Wsh[n][k0 + tg + 8];
        }
#pragma unroll
        for (int m = 0; m < 2; m++)
#pragma unroll
            for (int f = 0; f < 8; f++)
                mma_f16(acc[m][f], a[m], b[f]);
    }

    // epilogue: bias + relu, * ns, fp16 store (pad rows: ns=0 -> stay 0)
#pragma unroll
    for (int m = 0; m < 2; m++) {
        int ra = row0 + wm + m * 16 + g;
        int rb = ra + 8;
        float sa = ns[ra];
        float sb = ns[rb];
#pragma unroll
        for (int f = 0; f < 8; f++) {
            int n  = wn + f * 8 + tg;
            float b0 = __ldg(bias + n);
            float b1 = __ldg(bias + n + 1);
            float v0 = fmaxf(acc[m][f][0] + b0, 0.0f) * sa;
            float v1 = fmaxf(acc[m][f][1] + b1, 0.0f) * sa;
            float v2 = fmaxf(acc[m][f][2] + b0, 0.0f) * sb;
            float v3 = fmaxf(acc[m][f][3] + b1, 0.0f) * sb;
            *(__half2*)(Out + (size_t)ra * DD + n) = __floats2half2_rn(v0, v1);
            *(__half2*)(Out + (size_t)rb * DD + n) = __floats2half2_rn(v2, v3);
        }
    }
}

// ------------------------- layer-2 folded reduce ---------------------------
// vec[c] = sum_s c[s] * X[s][c]
#define WR_ROWS 784
__global__ void wreduce_kernel(const __half* __restrict__ X,
                               const float* __restrict__ cf,
                               float* __restrict__ vec) {
    __shared__ float sm[256];
    int col = threadIdx.x & 127;
    int ph  = threadIdx.x >> 7;
    int r0  = blockIdx.x * WR_ROWS;
    int rend = min(r0 + WR_ROWS, NN);
    float s = 0.0f;
    for (int r = r0 + ph; r < rend; r += 2)
        s = fmaf(cf[r], __half2float(X[(size_t)r * DD + col]), s);
    sm[threadIdx.x] = s;
    __syncthreads();
    if (ph == 0)
        atomicAdd(&vec[col], sm[col] + sm[col + 128]);
}

// ------------------------- final micro-GEMM: out = (vec/N) @ W2 + b2 -------
__global__ void final_kernel(const float* __restrict__ W2,
                             const float* __restrict__ b2,
                             const float* __restrict__ vec,
                             float* __restrict__ out) {
    __shared__ float v[DD];
    int c = threadIdx.x;
    v[c] = vec[c] * (1.0f / (float)NN);
    __syncthreads();
    float acc = b2[c];
#pragma unroll 8
    for (int k = 0; k < DD; k++)
        acc = fmaf(v[k], W2[(size_t)k * DD + c], acc);
    out[c] = acc;
}

// ===========================================================================
extern "C" void kernel_launch(void* const* d_in, const int* in_sizes, int n_in,
                              void* d_out, int out_size) {
    const float* h   = (const float*)d_in[0];
    const int*   src = (const int*)d_in[1];   // JAX demotes int64 -> int32
    const int*   dst = (const int*)d_in[2];
    const float* W0 = (const float*)d_in[3];
    const float* b0 = (const float*)d_in[4];
    const float* W1 = (const float*)d_in[5];
    const float* b1 = (const float*)d_in[6];
    const float* W2 = (const float*)d_in[7];
    const float* b2 = (const float*)d_in[8];
    float* out = (float*)d_out;

    void *pX, *pY, *pAGG, *pns, *pnd, *pc, *pcnt2, *pincl, *pcur, *pesrc,
         *pbsum, *pvec, *pWt0, *pWt1;
    cudaGetSymbolAddress(&pX,    g_X);
    cudaGetSymbolAddress(&pY,    g_Y);
    cudaGetSymbolAddress(&pAGG,  g_AGG);
    cudaGetSymbolAddress(&pns,   g_ns);
    cudaGetSymbolAddress(&pnd,   g_nd);
    cudaGetSymbolAddress(&pc,    g_c);
    cudaGetSymbolAddress(&pcnt2, g_cnt2);
    cudaGetSymbolAddress(&pincl, g_incl);
    cudaGetSymbolAddress(&pcur,  g_cur);
    cudaGetSymbolAddress(&pesrc, g_esrc);
    cudaGetSymbolAddress(&pbsum, g_bsum);
    cudaGetSymbolAddress(&pvec,  g_vec);
    cudaGetSymbolAddress(&pWt0,  g_Wt0);
    cudaGetSymbolAddress(&pWt1,  g_Wt1);
    __half* X    = (__half*)pX;
    __half* Y    = (__half*)pY;
    __half* AGG  = (__half*)pAGG;
    float*  ns   = (float*)pns;
    float*  nd   = (float*)pnd;
    float*  cf   = (float*)pc;
    int*    cnt2 = (int*)pcnt2;
    int*    incl = (int*)pincl;
    int*    cur  = (int*)pcur;
    int*    esrc = (int*)pesrc;
    int*    bsum = (int*)pbsum;
    float*  vec  = (float*)pvec;
    __half* Wt0  = (__half*)pWt0;
    __half* Wt1  = (__half*)pWt1;

    static int smemSet = 0;
    const int gemmSmem = 2 * 128 * SPAD * sizeof(__half);   // 69632 B
    if (!smemSet) {
        cudaFuncSetAttribute(gemm_f16_kernel,
                             cudaFuncAttributeMaxDynamicSharedMemorySize, gemmSmem);
        smemSet = 1;
    }

    const int nScanBlocks = (NN + 1023) / 1024;   // 98

    // --- degrees, norms, CSR-by-dst, fold coefficients ---
    cudaMemsetAsync(cnt2, 0, 2 * NN * sizeof(int));
    cudaMemsetAsync(cf, 0, NN * sizeof(float));
    hist_kernel<<<(NE + 255) / 256, 256>>>(src, dst, cnt2);
    scan1_kernel<<<nScanBlocks, 256>>>(cnt2 + NN, incl, bsum);
    scan2_kernel<<<1, 128>>>(bsum, nScanBlocks);
    scan3_kernel<<<(NN + 255) / 256, 256>>>(incl, bsum, cnt2, cur, ns, nd);
    fill_kernel<<<(NE + 255) / 256, 256>>>(src, dst, nd, cur, esrc, cf);

    // --- weight prep + X0 = half(h * ns) ---
    prep_kernel<<<64, 256>>>(W0, W1, Wt0, Wt1);
    conv_kernel<<<(NN * DD / 4 + 255) / 256, 256>>>(h, ns, X);

    const int gatherBlocks = (NN * 32 + 255) / 256;   // 12500
    const int gemmBlocks   = NN_PAD / 128;            // 782

    // --- layer 0: X -gather-> AGG -gemm-> Y ---
    gather_kernel<<<gatherBlocks, 256>>>(X, nd, incl, cnt2, esrc, AGG);
    gemm_f16_kernel<<<gemmBlocks, 256, gemmSmem>>>(AGG, Wt0, b0, ns, Y);

    // --- layer 1: Y -gather-> AGG -gemm-> X ---
    gather_kernel<<<gatherBlocks, 256>>>(Y, nd, incl, cnt2, esrc, AGG);
    gemm_f16_kernel<<<gemmBlocks, 256, gemmSmem>>>(AGG, Wt1, b1, ns, X);

    // --- layer 2 (folded): vec = sum_s c[s]*X[s]; out = (vec/N) @ W2 + b2 ---
    cudaMemsetAsync(vec, 0, DD * sizeof(float));
    wreduce_kernel<<<(NN + WR_ROWS - 1) / WR_ROWS, 256>>>(X, cf, vec);
    final_kernel<<<1, DD>>>(W2, b2, vec, out);

    (void)in_sizes; (void)n_in; (void)out_size;
}

// round 8
// speedup vs baseline: 4.1345x; 1.0742x over previous
#include <cuda_runtime.h>
#include <cuda_fp16.h>
#include <cstdint>

#define NN 100000
#define NN_PAD 100096          // multiple of 128
#define NE 1600000
#define DD 128
#define SPAD 136

// ------------------------- scratch (device globals) ------------------------
__device__ __half g_X  [(size_t)NN_PAD * DD];  // fp16 features (ping)
__device__ __half g_Y  [(size_t)NN_PAD * DD];  // fp16 features (pong)
__device__ __half g_AGG[(size_t)NN_PAD * DD];  // fp16 aggregated (pad rows stay 0)
__device__ float  g_ns  [NN_PAD];              // norm_src (pad rows stay 0)
__device__ float  g_nd  [NN];
__device__ float  g_c   [NN_PAD];              // layer-2 fold coeffs (pads stay 0)
__device__ int    g_cnt2[2 * NN];              // [0,NN): src deg, [NN,2NN): dst deg
__device__ int    g_incl[NN];
__device__ int    g_cur [NN];
__device__ int    g_esrc[NE];
__device__ int    g_bsum[128];
__device__ float  g_vec [DD];
__device__ __half g_Wt0[DD * DD];              // W0^T fp16 [n][k]
__device__ __half g_Wt1[DD * DD];              // W1^T fp16 [n][k]

// ------------------------- histogram ---------------------------------------
__global__ void hist_kernel(const int* __restrict__ src,
                            const int* __restrict__ dst,
                            int* __restrict__ cnt2) {
    int i = blockIdx.x * blockDim.x + threadIdx.x;
    if (i < NE) {
        atomicAdd(&cnt2[src[i]], 1);
        atomicAdd(&cnt2[NN + dst[i]], 1);
    }
}

// ------------------------- scan (chunk=1024) -------------------------------
__global__ void scan1_kernel(const int* __restrict__ cnt,
                             int* __restrict__ incl, int* __restrict__ bsum) {
    __shared__ int s[256];
    int b = blockIdx.x, t = threadIdx.x;
    int base = b * 1024 + t * 4;
    int v0 = (base + 0 < NN) ? cnt[base + 0] : 0;
    int v1 = (base + 1 < NN) ? cnt[base + 1] : 0;
    int v2 = (base + 2 < NN) ? cnt[base + 2] : 0;
    int v3 = (base + 3 < NN) ? cnt[base + 3] : 0;
    int l1 = v0 + v1, l2 = l1 + v2, l3 = l2 + v3;
    s[t] = l3;
    __syncthreads();
    for (int off = 1; off < 256; off <<= 1) {
        int x = (t >= off) ? s[t - off] : 0;
        __syncthreads();
        s[t] += x;
        __syncthreads();
    }
    int prev = t ? s[t - 1] : 0;
    if (base + 0 < NN) incl[base + 0] = prev + v0;
    if (base + 1 < NN) incl[base + 1] = prev + l1;
    if (base + 2 < NN) incl[base + 2] = prev + l2;
    if (base + 3 < NN) incl[base + 3] = prev + l3;
    if (t == 255) bsum[b] = s[255];
}

__global__ void scan2_kernel(int* __restrict__ bsum, int nb) {
    __shared__ int s[128];
    int t = threadIdx.x;
    int v = (t < nb) ? bsum[t] : 0;
    s[t] = v;
    __syncthreads();
    for (int off = 1; off < 128; off <<= 1) {
        int x = (t >= off) ? s[t - off] : 0;
        __syncthreads();
        s[t] += x;
        __syncthreads();
    }
    if (t < nb) bsum[t] = s[t] - v;   // exclusive
}

// incl finalize + cursors + degree norms (norm fused in)
__global__ void scan3_kernel(int* __restrict__ incl, const int* __restrict__ bsum,
                             const int* __restrict__ cnt2,
                             int* __restrict__ cur,
                             float* __restrict__ ns, float* __restrict__ nd) {
    int i = blockIdx.x * blockDim.x + threadIdx.x;
    if (i < NN) {
        int cd = cnt2[NN + i];
        int v  = incl[i] + bsum[i >> 10];
        incl[i] = v;
        cur[i]  = v - cd;
        ns[i] = rsqrtf(fmaxf((float)cnt2[i], 1.0f));
        nd[i] = rsqrtf(fmaxf((float)cd, 1.0f));
    }
}

// CSR fill + layer-2 fold coefficient c[src] += nd[dst]
__global__ void fill_kernel(const int* __restrict__ src, const int* __restrict__ dst,
                            const float* __restrict__ nd,
                            int* __restrict__ cur, int* __restrict__ esrc,
                            float* __restrict__ c) {
    int i = blockIdx.x * blockDim.x + threadIdx.x;
    if (i < NE) {
        int s = src[i], d = dst[i];
        int pos = atomicAdd(&cur[d], 1);
        esrc[pos] = s;
        atomicAdd(&c[s], nd[d]);
    }
}

// ------------------------- h -> fp16 prescaled by ns -----------------------
__global__ void conv_kernel(const float* __restrict__ h,
                            const float* __restrict__ ns,
                            __half* __restrict__ X) {
    int i = blockIdx.x * blockDim.x + threadIdx.x;   // float4 index
    if (i < NN * DD / 4) {
        int row = i >> 5;
        float s = ns[row];
        float4 v = ((const float4*)h)[i];
        __half2 a = __floats2half2_rn(v.x * s, v.y * s);
        __half2 b = __floats2half2_rn(v.z * s, v.w * s);
        uint2 u;
        u.x = *(uint32_t*)&a;
        u.y = *(uint32_t*)&b;
        ((uint2*)X)[i] = u;
    }
}

// ------------------------- W0,W1 -> W^T fp16 -------------------------------
__global__ void prep_kernel(const float* __restrict__ W0, const float* __restrict__ W1,
                            __half* __restrict__ Wt0, __half* __restrict__ Wt1) {
    int i = blockIdx.x * blockDim.x + threadIdx.x;
    if (i < DD * DD) {
        int k = i >> 7, n = i & 127;
        Wt0[n * DD + k] = __float2half(W0[i]);
        Wt1[n * DD + k] = __float2half(W1[i]);
    }
}

// ------------------------- gather SpMM (fp16 in/out, fp32 acc) -------------
// Warp per node, 8 edges/iter: half-warp pr takes even/odd edge of each pair,
// each lane LDG.128 (8 halves). Cross-half combine via shfl_xor(16).
__global__ void gather_kernel(const __half* __restrict__ Xh,
                              const float* __restrict__ nd,
                              const int* __restrict__ incl,
                              const int* __restrict__ cnt2,
                              const int* __restrict__ esrc,
                              __half* __restrict__ outp) {
    const int lane  = threadIdx.x & 31;
    const int pr    = lane >> 4;          // 0 or 1
    const int li    = lane & 15;          // 0..15
    const int warp0 = (blockIdx.x * blockDim.x + threadIdx.x) >> 5;
    const int nwarp = (gridDim.x * blockDim.x) >> 5;
    const uint4* __restrict__ Xv = (const uint4*)Xh;   // 16 x uint4 per row

    for (int node = warp0; node < NN; node += nwarp) {
        int end = incl[node];
        int beg = end - cnt2[NN + node];
        float acc[8];
#pragma unroll
        for (int i = 0; i < 8; i++) acc[i] = 0.0f;

#define ACC4(u) { \
        float2 f0 = __half22float2(*(__half2*)&(u).x); \
        float2 f1 = __half22float2(*(__half2*)&(u).y); \
        float2 f2 = __half22float2(*(__half2*)&(u).z); \
        float2 f3 = __half22float2(*(__half2*)&(u).w); \
        acc[0] += f0.x; acc[1] += f0.y; acc[2] += f1.x; acc[3] += f1.y; \
        acc[4] += f2.x; acc[5] += f2.y; acc[6] += f3.x; acc[7] += f3.y; }

        int e = beg;
        for (; e + 8 <= end; e += 8) {
            int sA = esrc[e + 0 + pr];
            int sB = esrc[e + 2 + pr];
            int sC = esrc[e + 4 + pr];
            int sD = esrc[e + 6 + pr];
            uint4 uA = Xv[(size_t)sA * 16 + li];
            uint4 uB = Xv[(size_t)sB * 16 + li];
            uint4 uC = Xv[(size_t)sC * 16 + li];
            uint4 uD = Xv[(size_t)sD * 16 + li];
            ACC4(uA) ACC4(uB) ACC4(uC) ACC4(uD)
        }
        for (; e < end; e += 2) {
            int idx = e + pr;
            if (idx < end) {
                int s = esrc[idx];
                uint4 u = Xv[(size_t)s * 16 + li];
                ACC4(u)
            }
        }
#undef ACC4
        // combine the two half-warps
#pragma unroll
        for (int i = 0; i < 8; i++)
            acc[i] += __shfl_xor_sync(0xffffffff, acc[i], 16);

        if (pr == 0) {
            float sd = nd[node];
            __half2 h0 = __floats2half2_rn(acc[0] * sd, acc[1] * sd);
            __half2 h1 = __floats2half2_rn(acc[2] * sd, acc[3] * sd);
            __half2 h2 = __floats2half2_rn(acc[4] * sd, acc[5] * sd);
            __half2 h3 = __floats2half2_rn(acc[6] * sd, acc[7] * sd);
            uint4 u;
            u.x = *(uint32_t*)&h0; u.y = *(uint32_t*)&h1;
            u.z = *(uint32_t*)&h2; u.w = *(uint32_t*)&h3;
            ((uint4*)outp)[(size_t)node * 16 + li] = u;
        }
    }
}

// ------------------------- fp16 MMA GEMM core ------------------------------
__device__ __forceinline__ void mma_f16(float* d, const uint32_t* a, const uint32_t* b) {
    asm volatile("mma.sync.aligned.m16n8k16.row.col.f32.f16.f16.f32 "
                 "{%0,%1,%2,%3}, {%4,%5,%6,%7}, {%8,%9}, {%0,%1,%2,%3};"
                 : "+f"(d[0]), "+f"(d[1]), "+f"(d[2]), "+f"(d[3])
                 : "r"(a[0]), "r"(a[1]), "r"(a[2]), "r"(a[3]),
                   "r"(b[0]), "r"(b[1]));
}

// FINAL=0: Out[r,:] = half( relu(A[r,:]@W + b) * ns[r] )
// FINAL=1: vec[c] += sum_r ns[r]*cf[r]*relu(A[r,:]@W + b)[c]   (no Out store)
template <int FINAL>
__global__ __launch_bounds__(256)
void gemm_f16_kernel(const __half* __restrict__ A,
                     const __half* __restrict__ Wt, const float* __restrict__ bias,
                     const float* __restrict__ ns, const float* __restrict__ cf,
                     __half* __restrict__ Out, float* __restrict__ vec) {
    extern __shared__ __half smem[];
    __half (*As)[SPAD]  = (__half(*)[SPAD])smem;
    __half (*Wsh)[SPAD] = (__half(*)[SPAD])(smem + 128 * SPAD);
    __shared__ float sv[DD];   // FINAL: per-block column sums

    const int t    = threadIdx.x;
    const int lane = t & 31;
    const int warp = t >> 5;
    const int row0 = blockIdx.x * 128;

    if (FINAL && t < DD) sv[t] = 0.0f;

#pragma unroll
    for (int j = 0; j < 8; j++) {
        int id = t + j * 256;
        int r  = id >> 4;
        int c8 = (id & 15) * 8;
        *(uint4*)&As[r][c8]  = *(const uint4*)(A  + (size_t)(row0 + r) * DD + c8);
        *(uint4*)&Wsh[r][c8] = *(const uint4*)(Wt + (size_t)r * DD + c8);
    }
    __syncthreads();

    const int wm = (warp & 3) * 32;
    const int wn = (warp >> 2) * 64;
    const int g  = lane >> 2;
    const int tg = (lane & 3) * 2;

    float acc[2][8][4];
#pragma unroll
    for (int m = 0; m < 2; m++)
#pragma unroll
        for (int f = 0; f < 8; f++)
#pragma unroll
            for (int i = 0; i < 4; i++) acc[m][f][i] = 0.0f;

#pragma unroll
    for (int ks = 0; ks < 8; ks++) {
        const int k0 = ks * 16;
        uint32_t a[2][4];
#pragma unroll
        for (int m = 0; m < 2; m++) {
            int r = wm + m * 16 + g;
            a[m][0] = *(const uint32_t*)&As[r][k0 + tg];
            a[m][1] = *(const uint32_t*)&As[r + 8][k0 + tg];
            a[m][2] = *(const uint32_t*)&As[r][k0 + tg + 8];
            a[m][3] = *(const uint32_t*)&As[r + 8][k0 + tg + 8];
        }
        uint32_t b[8][2];
#pragma unroll
        for (int f = 0; f < 8; f++) {
            int n = wn + f * 8 + g;
            b[f][0] = *(const uint32_t*)&Wsh[n][k0 + tg];
            b[f][1] = *(const uint32_t*)&Wsh[n][k0 + tg + 8];
        }
#pragma unroll
        for (int m = 0; m < 2; m++)
#pragma unroll
            for (int f = 0; f < 8; f++)
                mma_f16(acc[m][f], a[m], b[f]);
    }

#pragma unroll
    for (int m = 0; m < 2; m++) {
        int ra = row0 + wm + m * 16 + g;
        int rb = ra + 8;
        float sa = ns[ra];
        float sb = ns[rb];
        if (FINAL) { sa *= cf[ra]; sb *= cf[rb]; }
#pragma unroll
        for (int f = 0; f < 8; f++) {
            int n  = wn + f * 8 + tg;
            float b0 = __ldg(bias + n);
            float b1 = __ldg(bias + n + 1);
            float v0 = fmaxf(acc[m][f][0] + b0, 0.0f) * sa;
            float v1 = fmaxf(acc[m][f][1] + b1, 0.0f) * sa;
            float v2 = fmaxf(acc[m][f][2] + b0, 0.0f) * sb;
            float v3 = fmaxf(acc[m][f][3] + b1, 0.0f) * sb;
            if (!FINAL) {
                *(__half2*)(Out + (size_t)ra * DD + n) = __floats2half2_rn(v0, v1);
                *(__half2*)(Out + (size_t)rb * DD + n) = __floats2half2_rn(v2, v3);
            } else {
                float c0 = v0 + v2;     // column n
                float c1 = v1 + v3;     // column n+1
                // reduce over the 8 row-groups (lanes stride 4)
#pragma unroll
                for (int o = 4; o < 32; o <<= 1) {
                    c0 += __shfl_xor_sync(0xffffffff, c0, o);
                    c1 += __shfl_xor_sync(0xffffffff, c1, o);
                }
                if (g == 0) {
                    atomicAdd(&sv[n], c0);
                    atomicAdd(&sv[n + 1], c1);
                }
            }
        }
    }

    if (FINAL) {
        __syncthreads();
        if (t < DD) atomicAdd(&vec[t], sv[t]);
    }
}

// ------------------------- final micro-GEMM: out = (vec/N) @ W2 + b2 -------
__global__ void final_kernel(const float* __restrict__ W2,
                             const float* __restrict__ b2,
                             const float* __restrict__ vec,
                             float* __restrict__ out) {
    __shared__ float v[DD];
    int c = threadIdx.x;
    v[c] = vec[c] * (1.0f / (float)NN);
    __syncthreads();
    float acc = b2[c];
#pragma unroll 8
    for (int k = 0; k < DD; k++)
        acc = fmaf(v[k], W2[(size_t)k * DD + c], acc);
    out[c] = acc;
}

// ===========================================================================
extern "C" void kernel_launch(void* const* d_in, const int* in_sizes, int n_in,
                              void* d_out, int out_size) {
    const float* h   = (const float*)d_in[0];
    const int*   src = (const int*)d_in[1];   // JAX demotes int64 -> int32
    const int*   dst = (const int*)d_in[2];
    const float* W0 = (const float*)d_in[3];
    const float* b0 = (const float*)d_in[4];
    const float* W1 = (const float*)d_in[5];
    const float* b1 = (const float*)d_in[6];
    const float* W2 = (const float*)d_in[7];
    const float* b2 = (const float*)d_in[8];
    float* out = (float*)d_out;

    void *pX, *pY, *pAGG, *pns, *pnd, *pc, *pcnt2, *pincl, *pcur, *pesrc,
         *pbsum, *pvec, *pWt0, *pWt1;
    cudaGetSymbolAddress(&pX,    g_X);
    cudaGetSymbolAddress(&pY,    g_Y);
    cudaGetSymbolAddress(&pAGG,  g_AGG);
    cudaGetSymbolAddress(&pns,   g_ns);
    cudaGetSymbolAddress(&pnd,   g_nd);
    cudaGetSymbolAddress(&pc,    g_c);
    cudaGetSymbolAddress(&pcnt2, g_cnt2);
    cudaGetSymbolAddress(&pincl, g_incl);
    cudaGetSymbolAddress(&pcur,  g_cur);
    cudaGetSymbolAddress(&pesrc, g_esrc);
    cudaGetSymbolAddress(&pbsum, g_bsum);
    cudaGetSymbolAddress(&pvec,  g_vec);
    cudaGetSymbolAddress(&pWt0,  g_Wt0);
    cudaGetSymbolAddress(&pWt1,  g_Wt1);
    __half* X    = (__half*)pX;
    __half* Y    = (__half*)pY;
    __half* AGG  = (__half*)pAGG;
    float*  ns   = (float*)pns;
    float*  nd   = (float*)pnd;
    float*  cf   = (float*)pc;
    int*    cnt2 = (int*)pcnt2;
    int*    incl = (int*)pincl;
    int*    cur  = (int*)pcur;
    int*    esrc = (int*)pesrc;
    int*    bsum = (int*)pbsum;
    float*  vec  = (float*)pvec;
    __half* Wt0  = (__half*)pWt0;
    __half* Wt1  = (__half*)pWt1;

    static int smemSet = 0;
    const int gemmSmem = 2 * 128 * SPAD * sizeof(__half);   // 69632 B
    if (!smemSet) {
        cudaFuncSetAttribute(gemm_f16_kernel<0>,
                             cudaFuncAttributeMaxDynamicSharedMemorySize, gemmSmem);
        cudaFuncSetAttribute(gemm_f16_kernel<1>,
                             cudaFuncAttributeMaxDynamicSharedMemorySize, gemmSmem);
        smemSet = 1;
    }

    const int nScanBlocks = (NN + 1023) / 1024;   // 98

    // --- degrees, norms, CSR-by-dst, fold coefficients ---
    cudaMemsetAsync(cnt2, 0, 2 * NN * sizeof(int));
    cudaMemsetAsync(cf, 0, NN * sizeof(float));
    hist_kernel<<<(NE + 255) / 256, 256>>>(src, dst, cnt2);
    scan1_kernel<<<nScanBlocks, 256>>>(cnt2 + NN, incl, bsum);
    scan2_kernel<<<1, 128>>>(bsum, nScanBlocks);
    scan3_kernel<<<(NN + 255) / 256, 256>>>(incl, bsum, cnt2, cur, ns, nd);
    fill_kernel<<<(NE + 255) / 256, 256>>>(src, dst, nd, cur, esrc, cf);

    // --- weight prep + X0 = half(h * ns) ---
    prep_kernel<<<64, 256>>>(W0, W1, Wt0, Wt1);
    conv_kernel<<<(NN * DD / 4 + 255) / 256, 256>>>(h, ns, X);

    const int gatherBlocks = (NN * 32 + 255) / 256;   // 12500
    const int gemmBlocks   = NN_PAD / 128;            // 782

    // --- layer 0: X -gather-> AGG -gemm-> Y ---
    gather_kernel<<<gatherBlocks, 256>>>(X, nd, incl, cnt2, esrc, AGG);
    gemm_f16_kernel<0><<<gemmBlocks, 256, gemmSmem>>>(AGG, Wt0, b0, ns, cf, Y, vec);

    // --- layer 1 + folded layer 2: Y -gather-> AGG -gemm+reduce-> vec ---
    gather_kernel<<<gatherBlocks, 256>>>(Y, nd, incl, cnt2, esrc, AGG);
    cudaMemsetAsync(vec, 0, DD * sizeof(float));
    gemm_f16_kernel<1><<<gemmBlocks, 256, gemmSmem>>>(AGG, Wt1, b1, ns, cf, X, vec);

    // --- out = (vec/N) @ W2 + b2 ---
    final_kernel<<<1, DD>>>(W2, b2, vec, out);

    (void)in_sizes; (void)n_in; (void)out_size;
}

// round 10
// speedup vs baseline: 4.6566x; 1.1263x over previous
#include <cuda_runtime.h>
#include <cuda_fp16.h>
#include <cstdint>

#define NN 100000
#define NN_PAD 100096          // multiple of 128
#define NE 1600000
#define DD 128
#define SPAD 136

// ------------------------- scratch (device globals) ------------------------
__device__ __half g_X  [(size_t)NN_PAD * DD];  // fp16 features (ping)
__device__ __half g_Y  [(size_t)NN_PAD * DD];  // fp16 features (pong)
__device__ __half g_AGG[(size_t)NN_PAD * DD];  // fp16 aggregated (pad rows stay 0)
__device__ float  g_ns  [NN_PAD];              // norm_src (pad rows stay 0)
__device__ float  g_nd  [NN];
__device__ float  g_c   [NN_PAD];              // layer-2 fold coeffs (pads stay 0)
__device__ int    g_cnt2[2 * NN];              // [0,NN): src deg, [NN,2NN): dst deg
__device__ int    g_incl[NN];
__device__ int    g_cur [NN];
__device__ int    g_esrc[NE];
__device__ int    g_bsum[128];
__device__ float  g_vec [DD];
__device__ __half g_Wt0[DD * DD];              // W0^T fp16 [n][k]
__device__ __half g_Wt1[DD * DD];              // W1^T fp16 [n][k]

// ------------------------- histogram ---------------------------------------
__global__ void hist_kernel(const int* __restrict__ src,
                            const int* __restrict__ dst,
                            int* __restrict__ cnt2) {
    int i = blockIdx.x * blockDim.x + threadIdx.x;
    if (i < NE) {
        atomicAdd(&cnt2[src[i]], 1);
        atomicAdd(&cnt2[NN + dst[i]], 1);
    }
}

// ------------------------- scan (chunk=1024) -------------------------------
__global__ void scan1_kernel(const int* __restrict__ cnt,
                             int* __restrict__ incl, int* __restrict__ bsum) {
    __shared__ int s[256];
    int b = blockIdx.x, t = threadIdx.x;
    int base = b * 1024 + t * 4;
    int v0 = (base + 0 < NN) ? cnt[base + 0] : 0;
    int v1 = (base + 1 < NN) ? cnt[base + 1] : 0;
    int v2 = (base + 2 < NN) ? cnt[base + 2] : 0;
    int v3 = (base + 3 < NN) ? cnt[base + 3] : 0;
    int l1 = v0 + v1, l2 = l1 + v2, l3 = l2 + v3;
    s[t] = l3;
    __syncthreads();
    for (int off = 1; off < 256; off <<= 1) {
        int x = (t >= off) ? s[t - off] : 0;
        __syncthreads();
        s[t] += x;
        __syncthreads();
    }
    int prev = t ? s[t - 1] : 0;
    if (base + 0 < NN) incl[base + 0] = prev + v0;
    if (base + 1 < NN) incl[base + 1] = prev + l1;
    if (base + 2 < NN) incl[base + 2] = prev + l2;
    if (base + 3 < NN) incl[base + 3] = prev + l3;
    if (t == 255) bsum[b] = s[255];
}

__global__ void scan2_kernel(int* __restrict__ bsum, int nb) {
    __shared__ int s[128];
    int t = threadIdx.x;
    int v = (t < nb) ? bsum[t] : 0;
    s[t] = v;
    __syncthreads();
    for (int off = 1; off < 128; off <<= 1) {
        int x = (t >= off) ? s[t - off] : 0;
        __syncthreads();
        s[t] += x;
        __syncthreads();
    }
    if (t < nb) bsum[t] = s[t] - v;   // exclusive
}

// incl finalize + cursors + degree norms
__global__ void scan3_kernel(int* __restrict__ incl, const int* __restrict__ bsum,
                             const int* __restrict__ cnt2,
                             int* __restrict__ cur,
                             float* __restrict__ ns, float* __restrict__ nd) {
    int i = blockIdx.x * blockDim.x + threadIdx.x;
    if (i < NN) {
        int cd = cnt2[NN + i];
        int v  = incl[i] + bsum[i >> 10];
        incl[i] = v;
        cur[i]  = v - cd;
        ns[i] = rsqrtf(fmaxf((float)cnt2[i], 1.0f));
        nd[i] = rsqrtf(fmaxf((float)cd, 1.0f));
    }
}

// CSR fill + layer-2 fold coefficient c[src] += nd[dst]
__global__ void fill_kernel(const int* __restrict__ src, const int* __restrict__ dst,
                            const float* __restrict__ nd,
                            int* __restrict__ cur, int* __restrict__ esrc,
                            float* __restrict__ c) {
    int i = blockIdx.x * blockDim.x + threadIdx.x;
    if (i < NE) {
        int s = src[i], d = dst[i];
        int pos = atomicAdd(&cur[d], 1);
        esrc[pos] = s;
        atomicAdd(&c[s], nd[d]);
    }
}

// ------------------------- h -> fp16 prescaled by ns -----------------------
__global__ void conv_kernel(const float* __restrict__ h,
                            const float* __restrict__ ns,
                            __half* __restrict__ X) {
    int i = blockIdx.x * blockDim.x + threadIdx.x;   // float4 index
    if (i < NN * DD / 4) {
        int row = i >> 5;
        float s = ns[row];
        float4 v = ((const float4*)h)[i];
        __half2 a = __floats2half2_rn(v.x * s, v.y * s);
        __half2 b = __floats2half2_rn(v.z * s, v.w * s);
        uint2 u;
        u.x = *(uint32_t*)&a;
        u.y = *(uint32_t*)&b;
        ((uint2*)X)[i] = u;
    }
}

// ------------------------- W0,W1 -> W^T fp16 -------------------------------
__global__ void prep_kernel(const float* __restrict__ W0, const float* __restrict__ W1,
                            __half* __restrict__ Wt0, __half* __restrict__ Wt1) {
    int i = blockIdx.x * blockDim.x + threadIdx.x;
    if (i < DD * DD) {
        int k = i >> 7, n = i & 127;
        Wt0[n * DD + k] = __float2half(W0[i]);
        Wt1[n * DD + k] = __float2half(W1[i]);
    }
}

// ------------------------- gather SpMM (half2 accumulation) ----------------
// Warp per node, 8 edges/iter, HADD2 accumulation (4 ops per uint4).
// Cross-half combine via half2 shfl; fp32 only for the final nd scale.
__global__ void gather_kernel(const __half* __restrict__ Xh,
                              const float* __restrict__ nd,
                              const int* __restrict__ incl,
                              const int* __restrict__ cnt2,
                              const int* __restrict__ esrc,
                              __half* __restrict__ outp) {
    const int lane  = threadIdx.x & 31;
    const int pr    = lane >> 4;          // 0 or 1
    const int li    = lane & 15;          // 0..15
    const int warp0 = (blockIdx.x * blockDim.x + threadIdx.x) >> 5;
    const int nwarp = (gridDim.x * blockDim.x) >> 5;
    const uint4* __restrict__ Xv = (const uint4*)Xh;   // 16 x uint4 per row

    for (int node = warp0; node < NN; node += nwarp) {
        int end = incl[node];
        int beg = end - cnt2[NN + node];
        __half2 acc0 = __float2half2_rn(0.f);
        __half2 acc1 = acc0, acc2 = acc0, acc3 = acc0;

#define ACC4(u) { \
        acc0 = __hadd2(acc0, *(__half2*)&(u).x); \
        acc1 = __hadd2(acc1, *(__half2*)&(u).y); \
        acc2 = __hadd2(acc2, *(__half2*)&(u).z); \
        acc3 = __hadd2(acc3, *(__half2*)&(u).w); }

        int e = beg;
        for (; e + 8 <= end; e += 8) {
            int sA = esrc[e + 0 + pr];
            int sB = esrc[e + 2 + pr];
            int sC = esrc[e + 4 + pr];
            int sD = esrc[e + 6 + pr];
            uint4 uA = Xv[(size_t)sA * 16 + li];
            uint4 uB = Xv[(size_t)sB * 16 + li];
            uint4 uC = Xv[(size_t)sC * 16 + li];
            uint4 uD = Xv[(size_t)sD * 16 + li];
            ACC4(uA) ACC4(uB) ACC4(uC) ACC4(uD)
        }
        for (; e < end; e += 2) {
            int idx = e + pr;
            if (idx < end) {
                int s = esrc[idx];
                uint4 u = Xv[(size_t)s * 16 + li];
                ACC4(u)
            }
        }
#undef ACC4
        // combine the two half-warps (shuffle packed half2)
        acc0 = __hadd2(acc0, __shfl_xor_sync(0xffffffff, acc0, 16));
        acc1 = __hadd2(acc1, __shfl_xor_sync(0xffffffff, acc1, 16));
        acc2 = __hadd2(acc2, __shfl_xor_sync(0xffffffff, acc2, 16));
        acc3 = __hadd2(acc3, __shfl_xor_sync(0xffffffff, acc3, 16));

        if (pr == 0) {
            float sd = nd[node];
            float2 f0 = __half22float2(acc0);
            float2 f1 = __half22float2(acc1);
            float2 f2 = __half22float2(acc2);
            float2 f3 = __half22float2(acc3);
            __half2 h0 = __floats2half2_rn(f0.x * sd, f0.y * sd);
            __half2 h1 = __floats2half2_rn(f1.x * sd, f1.y * sd);
            __half2 h2 = __floats2half2_rn(f2.x * sd, f2.y * sd);
            __half2 h3 = __floats2half2_rn(f3.x * sd, f3.y * sd);
            uint4 u;
            u.x = *(uint32_t*)&h0; u.y = *(uint32_t*)&h1;
            u.z = *(uint32_t*)&h2; u.w = *(uint32_t*)&h3;
            ((uint4*)outp)[(size_t)node * 16 + li] = u;
        }
    }
}

// ------------------------- fp16 MMA GEMM core ------------------------------
__device__ __forceinline__ void mma_f16(float* d, const uint32_t* a, const uint32_t* b) {
    asm volatile("mma.sync.aligned.m16n8k16.row.col.f32.f16.f16.f32 "
                 "{%0,%1,%2,%3}, {%4,%5,%6,%7}, {%8,%9}, {%0,%1,%2,%3};"
                 : "+f"(d[0]), "+f"(d[1]), "+f"(d[2]), "+f"(d[3])
                 : "r"(a[0]), "r"(a[1]), "r"(a[2]), "r"(a[3]),
                   "r"(b[0]), "r"(b[1]));
}

// FINAL=0: Out[r,:] = half( relu(A[r,:]@W + b) * ns[r] )
// FINAL=1: vec[c] += sum_r ns[r]*cf[r]*relu(A[r,:]@W + b)[c]   (no Out store)
template <int FINAL>
__global__ __launch_bounds__(256)
void gemm_f16_kernel(const __half* __restrict__ A,
                     const __half* __restrict__ Wt, const float* __restrict__ bias,
                     const float* __restrict__ ns, const float* __restrict__ cf,
                     __half* __restrict__ Out, float* __restrict__ vec) {
    extern __shared__ __half smem[];
    __half (*As)[SPAD]  = (__half(*)[SPAD])smem;
    __half (*Wsh)[SPAD] = (__half(*)[SPAD])(smem + 128 * SPAD);
    __shared__ float sv[DD];   // FINAL: per-block column sums

    const int t    = threadIdx.x;
    const int lane = t & 31;
    const int warp = t >> 5;
    const int row0 = blockIdx.x * 128;

    if (FINAL && t < DD) sv[t] = 0.0f;

#pragma unroll
    for (int j = 0; j < 8; j++) {
        int id = t + j * 256;
        int r  = id >> 4;
        int c8 = (id & 15) * 8;
        *(uint4*)&As[r][c8]  = *(const uint4*)(A  + (size_t)(row0 + r) * DD + c8);
        *(uint4*)&Wsh[r][c8] = *(const uint4*)(Wt + (size_t)r * DD + c8);
    }
    __syncthreads();

    const int wm = (warp & 3) * 32;
    const int wn = (warp >> 2) * 64;
    const int g  = lane >> 2;
    const int tg = (lane & 3) * 2;

    float acc[2][8][4];
#pragma unroll
    for (int m = 0; m < 2; m++)
#pragma unroll
        for (int f = 0; f < 8; f++)
#pragma unroll
            for (int i = 0; i < 4; i++) acc[m][f][i] = 0.0f;

#pragma unroll
    for (int ks = 0; ks < 8; ks++) {
        const int k0 = ks * 16;
        uint32_t a[2][4];
#pragma unroll
        for (int m = 0; m < 2; m++) {
            int r = wm + m * 16 + g;
            a[m][0] = *(const uint32_t*)&As[r][k0 + tg];
            a[m][1] = *(const uint32_t*)&As[r + 8][k0 + tg];
            a[m][2] = *(const uint32_t*)&As[r][k0 + tg + 8];
            a[m][3] = *(const uint32_t*)&As[r + 8][k0 + tg + 8];
        }
        uint32_t b[8][2];
#pragma unroll
        for (int f = 0; f < 8; f++) {
            int n = wn + f * 8 + g;
            b[f][0] = *(const uint32_t*)&Wsh[n][k0 + tg];
            b[f][1] = *(const uint32_t*)&Wsh[n][k0 + tg + 8];
        }
#pragma unroll
        for (int m = 0; m < 2; m++)
#pragma unroll
            for (int f = 0; f < 8; f++)
                mma_f16(acc[m][f], a[m], b[f]);
    }

#pragma unroll
    for (int m = 0; m < 2; m++) {
        int ra = row0 + wm + m * 16 + g;
        int rb = ra + 8;
        float sa = ns[ra];
        float sb = ns[rb];
        if (FINAL) { sa *= cf[ra]; sb *= cf[rb]; }
#pragma unroll
        for (int f = 0; f < 8; f++) {
            int n  = wn + f * 8 + tg;
            float b0 = __ldg(bias + n);
            float b1 = __ldg(bias + n + 1);
            float v0 = fmaxf(acc[m][f][0] + b0, 0.0f) * sa;
            float v1 = fmaxf(acc[m][f][1] + b1, 0.0f) * sa;
            float v2 = fmaxf(acc[m][f][2] + b0, 0.0f) * sb;
            float v3 = fmaxf(acc[m][f][3] + b1, 0.0f) * sb;
            if (!FINAL) {
                *(__half2*)(Out + (size_t)ra * DD + n) = __floats2half2_rn(v0, v1);
                *(__half2*)(Out + (size_t)rb * DD + n) = __floats2half2_rn(v2, v3);
            } else {
                float c0 = v0 + v2;
                float c1 = v1 + v3;
#pragma unroll
                for (int o = 4; o < 32; o <<= 1) {
                    c0 += __shfl_xor_sync(0xffffffff, c0, o);
                    c1 += __shfl_xor_sync(0xffffffff, c1, o);
                }
                if (g == 0) {
                    atomicAdd(&sv[n], c0);
                    atomicAdd(&sv[n + 1], c1);
                }
            }
        }
    }

    if (FINAL) {
        __syncthreads();
        if (t < DD) atomicAdd(&vec[t], sv[t]);
    }
}

// ------------------------- final micro-GEMM: out = (vec/N) @ W2 + b2 -------
__global__ void final_kernel(const float* __restrict__ W2,
                             const float* __restrict__ b2,
                             const float* __restrict__ vec,
                             float* __restrict__ out) {
    __shared__ float v[DD];
    int c = threadIdx.x;
    v[c] = vec[c] * (1.0f / (float)NN);
    __syncthreads();
    float acc = b2[c];
#pragma unroll 8
    for (int k = 0; k < DD; k++)
        acc = fmaf(v[k], W2[(size_t)k * DD + c], acc);
    out[c] = acc;
}

// ===========================================================================
extern "C" void kernel_launch(void* const* d_in, const int* in_sizes, int n_in,
                              void* d_out, int out_size) {
    const float* h   = (const float*)d_in[0];
    const int*   src = (const int*)d_in[1];   // JAX demotes int64 -> int32
    const int*   dst = (const int*)d_in[2];
    const float* W0 = (const float*)d_in[3];
    const float* b0 = (const float*)d_in[4];
    const float* W1 = (const float*)d_in[5];
    const float* b1 = (const float*)d_in[6];
    const float* W2 = (const float*)d_in[7];
    const float* b2 = (const float*)d_in[8];
    float* out = (float*)d_out;

    void *pX, *pY, *pAGG, *pns, *pnd, *pc, *pcnt2, *pincl, *pcur, *pesrc,
         *pbsum, *pvec, *pWt0, *pWt1;
    cudaGetSymbolAddress(&pX,    g_X);
    cudaGetSymbolAddress(&pY,    g_Y);
    cudaGetSymbolAddress(&pAGG,  g_AGG);
    cudaGetSymbolAddress(&pns,   g_ns);
    cudaGetSymbolAddress(&pnd,   g_nd);
    cudaGetSymbolAddress(&pc,    g_c);
    cudaGetSymbolAddress(&pcnt2, g_cnt2);
    cudaGetSymbolAddress(&pincl, g_incl);
    cudaGetSymbolAddress(&pcur,  g_cur);
    cudaGetSymbolAddress(&pesrc, g_esrc);
    cudaGetSymbolAddress(&pbsum, g_bsum);
    cudaGetSymbolAddress(&pvec,  g_vec);
    cudaGetSymbolAddress(&pWt0,  g_Wt0);
    cudaGetSymbolAddress(&pWt1,  g_Wt1);
    __half* X    = (__half*)pX;
    __half* Y    = (__half*)pY;
    __half* AGG  = (__half*)pAGG;
    float*  ns   = (float*)pns;
    float*  nd   = (float*)pnd;
    float*  cf   = (float*)pc;
    int*    cnt2 = (int*)pcnt2;
    int*    incl = (int*)pincl;
    int*    cur  = (int*)pcur;
    int*    esrc = (int*)pesrc;
    int*    bsum = (int*)pbsum;
    float*  vec  = (float*)pvec;
    __half* Wt0  = (__half*)pWt0;
    __half* Wt1  = (__half*)pWt1;

    static int smemSet = 0;
    const int gemmSmem = 2 * 128 * SPAD * sizeof(__half);   // 69632 B
    if (!smemSet) {
        cudaFuncSetAttribute(gemm_f16_kernel<0>,
                             cudaFuncAttributeMaxDynamicSharedMemorySize, gemmSmem);
        cudaFuncSetAttribute(gemm_f16_kernel<1>,
                             cudaFuncAttributeMaxDynamicSharedMemorySize, gemmSmem);
        smemSet = 1;
    }

    const int nScanBlocks = (NN + 1023) / 1024;   // 98

    // --- degrees, norms, CSR-by-dst, fold coefficients ---
    cudaMemsetAsync(cnt2, 0, 2 * NN * sizeof(int));
    cudaMemsetAsync(cf, 0, NN * sizeof(float));
    hist_kernel<<<(NE + 255) / 256, 256>>>(src, dst, cnt2);
    scan1_kernel<<<nScanBlocks, 256>>>(cnt2 + NN, incl, bsum);
    scan2_kernel<<<1, 128>>>(bsum, nScanBlocks);
    scan3_kernel<<<(NN + 255) / 256, 256>>>(incl, bsum, cnt2, cur, ns, nd);
    fill_kernel<<<(NE + 255) / 256, 256>>>(src, dst, nd, cur, esrc, cf);

    // --- weight prep + X0 = half(h * ns) ---
    prep_kernel<<<64, 256>>>(W0, W1, Wt0, Wt1);
    conv_kernel<<<(NN * DD / 4 + 255) / 256, 256>>>(h, ns, X);

    const int gatherBlocks = (NN * 32 + 255) / 256;   // 12500
    const int gemmBlocks   = NN_PAD / 128;            // 782

    // --- layer 0: X -gather-> AGG -gemm-> Y ---
    gather_kernel<<<gatherBlocks, 256>>>(X, nd, incl, cnt2, esrc, AGG);
    gemm_f16_kernel<0><<<gemmBlocks, 256, gemmSmem>>>(AGG, Wt0, b0, ns, cf, Y, vec);

    // --- layer 1 + folded layer 2: Y -gather-> AGG -gemm+reduce-> vec ---
    gather_kernel<<<gatherBlocks, 256>>>(Y, nd, incl, cnt2, esrc, AGG);
    cudaMemsetAsync(vec, 0, DD * sizeof(float));
    gemm_f16_kernel<1><<<gemmBlocks, 256, gemmSmem>>>(AGG, Wt1, b1, ns, cf, X, vec);

    // --- out = (vec/N) @ W2 + b2 ---
    final_kernel<<<1, DD>>>(W2, b2, vec, out);

    (void)in_sizes; (void)n_in; (void)out_size;
}

// round 11
// speedup vs baseline: 4.7064x; 1.0107x over previous
#include <cuda_runtime.h>
#include <cuda_fp16.h>
#include <cstdint>

#define NN 100000
#define NN_PAD 100096          // multiple of 128
#define NE 1600000
#define DD 128
#define SPAD 136

// ------------------------- scratch (device globals) ------------------------
__device__ __half g_X  [(size_t)NN_PAD * DD];  // fp16 features (ping)
__device__ __half g_Y  [(size_t)NN_PAD * DD];  // fp16 features (pong)
__device__ __half g_AGG[(size_t)NN_PAD * DD];  // fp16 aggregated (pad rows stay 0)
__device__ float  g_ns  [NN_PAD];              // norm_src (pad rows stay 0)
__device__ float  g_nd  [NN];
__device__ float  g_c   [NN_PAD];              // layer-2 fold coeffs (pads stay 0)
__device__ int    g_cnt2[2 * NN];              // [0,NN): src deg, [NN,2NN): dst deg
__device__ int    g_incl[NN];
__device__ int    g_cur [NN];
__device__ int    g_esrc[NE];
__device__ int    g_bsum[128];
__device__ float  g_vec [DD];
__device__ __half g_Wt0[DD * DD];              // W0^T fp16 [n][k]
__device__ __half g_Wt1[DD * DD];              // W1^T fp16 [n][k]

// ------------------------- histogram ---------------------------------------
__global__ void hist_kernel(const int* __restrict__ src,
                            const int* __restrict__ dst,
                            int* __restrict__ cnt2) {
    int i = blockIdx.x * blockDim.x + threadIdx.x;
    if (i < NE) {
        atomicAdd(&cnt2[src[i]], 1);
        atomicAdd(&cnt2[NN + dst[i]], 1);
    }
}

// ------------------------- degree norms ------------------------------------
__global__ void norm_kernel(const int* __restrict__ cnt2,
                            float* __restrict__ ns, float* __restrict__ nd) {
    int i = blockIdx.x * blockDim.x + threadIdx.x;
    if (i < NN) {
        ns[i] = rsqrtf(fmaxf((float)cnt2[i], 1.0f));
        nd[i] = rsqrtf(fmaxf((float)cnt2[NN + i], 1.0f));
    }
}

// ------------------------- scan (chunk=1024) -------------------------------
__global__ void scan1_kernel(const int* __restrict__ cnt,
                             int* __restrict__ incl, int* __restrict__ bsum) {
    __shared__ int s[256];
    int b = blockIdx.x, t = threadIdx.x;
    int base = b * 1024 + t * 4;
    int v0 = (base + 0 < NN) ? cnt[base + 0] : 0;
    int v1 = (base + 1 < NN) ? cnt[base + 1] : 0;
    int v2 = (base + 2 < NN) ? cnt[base + 2] : 0;
    int v3 = (base + 3 < NN) ? cnt[base + 3] : 0;
    int l1 = v0 + v1, l2 = l1 + v2, l3 = l2 + v3;
    s[t] = l3;
    __syncthreads();
    for (int off = 1; off < 256; off <<= 1) {
        int x = (t >= off) ? s[t - off] : 0;
        __syncthreads();
        s[t] += x;
        __syncthreads();
    }
    int prev = t ? s[t - 1] : 0;
    if (base + 0 < NN) incl[base + 0] = prev + v0;
    if (base + 1 < NN) incl[base + 1] = prev + l1;
    if (base + 2 < NN) incl[base + 2] = prev + l2;
    if (base + 3 < NN) incl[base + 3] = prev + l3;
    if (t == 255) bsum[b] = s[255];
}

// finalize incl + cursors; each block computes its own chunk-prefix of bsum
__global__ void scan3_kernel(int* __restrict__ incl, const int* __restrict__ bsum,
                             const int* __restrict__ cnt2, int* __restrict__ cur) {
    __shared__ int red[256];
    int b = blockIdx.x, t = threadIdx.x;
    red[t] = (t < b) ? bsum[t] : 0;     // b <= 97 < 256
    __syncthreads();
    for (int off = 128; off > 0; off >>= 1) {
        if (t < off) red[t] += red[t + off];
        __syncthreads();
    }
    int offset = red[0];
    int base = b * 1024 + t * 4;
#pragma unroll
    for (int j = 0; j < 4; j++) {
        int i = base + j;
        if (i < NN) {
            int v = incl[i] + offset;
            incl[i] = v;
            cur[i]  = v - cnt2[NN + i];
        }
    }
}

// CSR fill + layer-2 fold coefficient c[src] += nd[dst]
__global__ void fill_kernel(const int* __restrict__ src, const int* __restrict__ dst,
                            const float* __restrict__ nd,
                            int* __restrict__ cur, int* __restrict__ esrc,
                            float* __restrict__ c) {
    int i = blockIdx.x * blockDim.x + threadIdx.x;
    if (i < NE) {
        int s = src[i], d = dst[i];
        int pos = atomicAdd(&cur[d], 1);
        esrc[pos] = s;
        atomicAdd(&c[s], nd[d]);
    }
}

// ------------------------- h -> fp16 prescaled by ns -----------------------
__global__ void conv_kernel(const float* __restrict__ h,
                            const float* __restrict__ ns,
                            __half* __restrict__ X) {
    int i = blockIdx.x * blockDim.x + threadIdx.x;   // float4 index
    if (i < NN * DD / 4) {
        int row = i >> 5;
        float s = ns[row];
        float4 v = ((const float4*)h)[i];
        __half2 a = __floats2half2_rn(v.x * s, v.y * s);
        __half2 b = __floats2half2_rn(v.z * s, v.w * s);
        uint2 u;
        u.x = *(uint32_t*)&a;
        u.y = *(uint32_t*)&b;
        ((uint2*)X)[i] = u;
    }
}

// ------------------------- W0,W1 -> W^T fp16 -------------------------------
__global__ void prep_kernel(const float* __restrict__ W0, const float* __restrict__ W1,
                            __half* __restrict__ Wt0, __half* __restrict__ Wt1) {
    int i = blockIdx.x * blockDim.x + threadIdx.x;
    if (i < DD * DD) {
        int k = i >> 7, n = i & 127;
        Wt0[n * DD + k] = __float2half(W0[i]);
        Wt1[n * DD + k] = __float2half(W1[i]);
    }
}

// ------------------------- gather SpMM (half2 accumulation) ----------------
__global__ void gather_kernel(const __half* __restrict__ Xh,
                              const float* __restrict__ nd,
                              const int* __restrict__ incl,
                              const int* __restrict__ cnt2,
                              const int* __restrict__ esrc,
                              __half* __restrict__ outp) {
    const int lane  = threadIdx.x & 31;
    const int pr    = lane >> 4;          // 0 or 1
    const int li    = lane & 15;          // 0..15
    const int warp0 = (blockIdx.x * blockDim.x + threadIdx.x) >> 5;
    const int nwarp = (gridDim.x * blockDim.x) >> 5;
    const uint4* __restrict__ Xv = (const uint4*)Xh;   // 16 x uint4 per row

    for (int node = warp0; node < NN; node += nwarp) {
        int end = incl[node];
        int beg = end - cnt2[NN + node];
        __half2 acc0 = __float2half2_rn(0.f);
        __half2 acc1 = acc0, acc2 = acc0, acc3 = acc0;

#define ACC4(u) { \
        acc0 = __hadd2(acc0, *(__half2*)&(u).x); \
        acc1 = __hadd2(acc1, *(__half2*)&(u).y); \
        acc2 = __hadd2(acc2, *(__half2*)&(u).z); \
        acc3 = __hadd2(acc3, *(__half2*)&(u).w); }

        int e = beg;
        for (; e + 8 <= end; e += 8) {
            int sA = esrc[e + 0 + pr];
            int sB = esrc[e + 2 + pr];
            int sC = esrc[e + 4 + pr];
            int sD = esrc[e + 6 + pr];
            uint4 uA = Xv[(size_t)sA * 16 + li];
            uint4 uB = Xv[(size_t)sB * 16 + li];
            uint4 uC = Xv[(size_t)sC * 16 + li];
            uint4 uD = Xv[(size_t)sD * 16 + li];
            ACC4(uA) ACC4(uB) ACC4(uC) ACC4(uD)
        }
        for (; e < end; e += 2) {
            int idx = e + pr;
            if (idx < end) {
                int s = esrc[idx];
                uint4 u = Xv[(size_t)s * 16 + li];
                ACC4(u)
            }
        }
#undef ACC4
        acc0 = __hadd2(acc0, __shfl_xor_sync(0xffffffff, acc0, 16));
        acc1 = __hadd2(acc1, __shfl_xor_sync(0xffffffff, acc1, 16));
        acc2 = __hadd2(acc2, __shfl_xor_sync(0xffffffff, acc2, 16));
        acc3 = __hadd2(acc3, __shfl_xor_sync(0xffffffff, acc3, 16));

        if (pr == 0) {
            float sd = nd[node];
            float2 f0 = __half22float2(acc0);
            float2 f1 = __half22float2(acc1);
            float2 f2 = __half22float2(acc2);
            float2 f3 = __half22float2(acc3);
            __half2 h0 = __floats2half2_rn(f0.x * sd, f0.y * sd);
            __half2 h1 = __floats2half2_rn(f1.x * sd, f1.y * sd);
            __half2 h2 = __floats2half2_rn(f2.x * sd, f2.y * sd);
            __half2 h3 = __floats2half2_rn(f3.x * sd, f3.y * sd);
            uint4 u;
            u.x = *(uint32_t*)&h0; u.y = *(uint32_t*)&h1;
            u.z = *(uint32_t*)&h2; u.w = *(uint32_t*)&h3;
            ((uint4*)outp)[(size_t)node * 16 + li] = u;
        }
    }
}

// ------------------------- fp16 MMA GEMM core ------------------------------
__device__ __forceinline__ void mma_f16(float* d, const uint32_t* a, const uint32_t* b) {
    asm volatile("mma.sync.aligned.m16n8k16.row.col.f32.f16.f16.f32 "
                 "{%0,%1,%2,%3}, {%4,%5,%6,%7}, {%8,%9}, {%0,%1,%2,%3};"
                 : "+f"(d[0]), "+f"(d[1]), "+f"(d[2]), "+f"(d[3])
                 : "r"(a[0]), "r"(a[1]), "r"(a[2]), "r"(a[3]),
                   "r"(b[0]), "r"(b[1]));
}

// FINAL=0: Out[r,:] = half( relu(A[r,:]@W + b) * ns[r] )
// FINAL=1: vec[c] += sum_r ns[r]*cf[r]*relu(A[r,:]@W + b)[c]
template <int FINAL>
__global__ __launch_bounds__(256)
void gemm_f16_kernel(const __half* __restrict__ A,
                     const __half* __restrict__ Wt, const float* __restrict__ bias,
                     const float* __restrict__ ns, const float* __restrict__ cf,
                     __half* __restrict__ Out, float* __restrict__ vec) {
    extern __shared__ __half smem[];
    __half (*As)[SPAD]  = (__half(*)[SPAD])smem;
    __half (*Wsh)[SPAD] = (__half(*)[SPAD])(smem + 128 * SPAD);
    __shared__ float sv[DD];

    const int t    = threadIdx.x;
    const int lane = t & 31;
    const int warp = t >> 5;
    const int row0 = blockIdx.x * 128;

    if (FINAL && t < DD) sv[t] = 0.0f;

#pragma unroll
    for (int j = 0; j < 8; j++) {
        int id = t + j * 256;
        int r  = id >> 4;
        int c8 = (id & 15) * 8;
        *(uint4*)&As[r][c8]  = *(const uint4*)(A  + (size_t)(row0 + r) * DD + c8);
        *(uint4*)&Wsh[r][c8] = *(const uint4*)(Wt + (size_t)r * DD + c8);
    }
    __syncthreads();

    const int wm = (warp & 3) * 32;
    const int wn = (warp >> 2) * 64;
    const int g  = lane >> 2;
    const int tg = (lane & 3) * 2;

    float acc[2][8][4];
#pragma unroll
    for (int m = 0; m < 2; m++)
#pragma unroll
        for (int f = 0; f < 8; f++)
#pragma unroll
            for (int i = 0; i < 4; i++) acc[m][f][i] = 0.0f;

#pragma unroll
    for (int ks = 0; ks < 8; ks++) {
        const int k0 = ks * 16;
        uint32_t a[2][4];
#pragma unroll
        for (int m = 0; m < 2; m++) {
            int r = wm + m * 16 + g;
            a[m][0] = *(const uint32_t*)&As[r][k0 + tg];
            a[m][1] = *(const uint32_t*)&As[r + 8][k0 + tg];
            a[m][2] = *(const uint32_t*)&As[r][k0 + tg + 8];
            a[m][3] = *(const uint32_t*)&As[r + 8][k0 + tg + 8];
        }
        uint32_t b[8][2];
#pragma unroll
        for (int f = 0; f < 8; f++) {
            int n = wn + f * 8 + g;
            b[f][0] = *(const uint32_t*)&Wsh[n][k0 + tg];
            b[f][1] = *(const uint32_t*)&Wsh[n][k0 + tg + 8];
        }
#pragma unroll
        for (int m = 0; m < 2; m++)
#pragma unroll
            for (int f = 0; f < 8; f++)
                mma_f16(acc[m][f], a[m], b[f]);
    }

#pragma unroll
    for (int m = 0; m < 2; m++) {
        int ra = row0 + wm + m * 16 + g;
        int rb = ra + 8;
        float sa = ns[ra];
        float sb = ns[rb];
        if (FINAL) { sa *= cf[ra]; sb *= cf[rb]; }
#pragma unroll
        for (int f = 0; f < 8; f++) {
            int n  = wn + f * 8 + tg;
            float b0 = __ldg(bias + n);
            float b1 = __ldg(bias + n + 1);
            float v0 = fmaxf(acc[m][f][0] + b0, 0.0f) * sa;
            float v1 = fmaxf(acc[m][f][1] + b1, 0.0f) * sa;
            float v2 = fmaxf(acc[m][f][2] + b0, 0.0f) * sb;
            float v3 = fmaxf(acc[m][f][3] + b1, 0.0f) * sb;
            if (!FINAL) {
                *(__half2*)(Out + (size_t)ra * DD + n) = __floats2half2_rn(v0, v1);
                *(__half2*)(Out + (size_t)rb * DD + n) = __floats2half2_rn(v2, v3);
            } else {
                float c0 = v0 + v2;
                float c1 = v1 + v3;
#pragma unroll
                for (int o = 4; o < 32; o <<= 1) {
                    c0 += __shfl_xor_sync(0xffffffff, c0, o);
                    c1 += __shfl_xor_sync(0xffffffff, c1, o);
                }
                if (g == 0) {
                    atomicAdd(&sv[n], c0);
                    atomicAdd(&sv[n + 1], c1);
                }
            }
        }
    }

    if (FINAL) {
        __syncthreads();
        if (t < DD) atomicAdd(&vec[t], sv[t]);
    }
}

// ------------------------- final micro-GEMM: out = (vec/N) @ W2 + b2 -------
__global__ void final_kernel(const float* __restrict__ W2,
                             const float* __restrict__ b2,
                             const float* __restrict__ vec,
                             float* __restrict__ out) {
    __shared__ float v[DD];
    int c = threadIdx.x;
    v[c] = vec[c] * (1.0f / (float)NN);
    __syncthreads();
    float acc = b2[c];
#pragma unroll 8
    for (int k = 0; k < DD; k++)
        acc = fmaf(v[k], W2[(size_t)k * DD + c], acc);
    out[c] = acc;
}

// ------------------------- stream/event infra (created at load time) -------
static cudaStream_t g_s2 = nullptr;
static cudaEvent_t  g_evA = nullptr, g_evB = nullptr, g_evC = nullptr;
static bool g_infraTried = false;

static void ensure_infra() {
    if (g_infraTried) return;
    g_infraTried = true;
    cudaStreamCreateWithFlags(&g_s2, cudaStreamNonBlocking);
    cudaEventCreateWithFlags(&g_evA, cudaEventDisableTiming);
    cudaEventCreateWithFlags(&g_evB, cudaEventDisableTiming);
    cudaEventCreateWithFlags(&g_evC, cudaEventDisableTiming);
}

namespace { struct InfraInit { InfraInit() { ensure_infra(); } } g_infraInit; }

// ===========================================================================
extern "C" void kernel_launch(void* const* d_in, const int* in_sizes, int n_in,
                              void* d_out, int out_size) {
    const float* h   = (const float*)d_in[0];
    const int*   src = (const int*)d_in[1];   // JAX demotes int64 -> int32
    const int*   dst = (const int*)d_in[2];
    const float* W0 = (const float*)d_in[3];
    const float* b0 = (const float*)d_in[4];
    const float* W1 = (const float*)d_in[5];
    const float* b1 = (const float*)d_in[6];
    const float* W2 = (const float*)d_in[7];
    const float* b2 = (const float*)d_in[8];
    float* out = (float*)d_out;

    void *pX, *pY, *pAGG, *pns, *pnd, *pc, *pcnt2, *pincl, *pcur, *pesrc,
         *pbsum, *pvec, *pWt0, *pWt1;
    cudaGetSymbolAddress(&pX,    g_X);
    cudaGetSymbolAddress(&pY,    g_Y);
    cudaGetSymbolAddress(&pAGG,  g_AGG);
    cudaGetSymbolAddress(&pns,   g_ns);
    cudaGetSymbolAddress(&pnd,   g_nd);
    cudaGetSymbolAddress(&pc,    g_c);
    cudaGetSymbolAddress(&pcnt2, g_cnt2);
    cudaGetSymbolAddress(&pincl, g_incl);
    cudaGetSymbolAddress(&pcur,  g_cur);
    cudaGetSymbolAddress(&pesrc, g_esrc);
    cudaGetSymbolAddress(&pbsum, g_bsum);
    cudaGetSymbolAddress(&pvec,  g_vec);
    cudaGetSymbolAddress(&pWt0,  g_Wt0);
    cudaGetSymbolAddress(&pWt1,  g_Wt1);
    __half* X    = (__half*)pX;
    __half* Y    = (__half*)pY;
    __half* AGG  = (__half*)pAGG;
    float*  ns   = (float*)pns;
    float*  nd   = (float*)pnd;
    float*  cf   = (float*)pc;
    int*    cnt2 = (int*)pcnt2;
    int*    incl = (int*)pincl;
    int*    cur  = (int*)pcur;
    int*    esrc = (int*)pesrc;
    int*    bsum = (int*)pbsum;
    float*  vec  = (float*)pvec;
    __half* Wt0  = (__half*)pWt0;
    __half* Wt1  = (__half*)pWt1;

    static int smemSet = 0;
    const int gemmSmem = 2 * 128 * SPAD * sizeof(__half);   // 69632 B
    if (!smemSet) {
        cudaFuncSetAttribute(gemm_f16_kernel<0>,
                             cudaFuncAttributeMaxDynamicSharedMemorySize, gemmSmem);
        cudaFuncSetAttribute(gemm_f16_kernel<1>,
                             cudaFuncAttributeMaxDynamicSharedMemorySize, gemmSmem);
        smemSet = 1;
    }

    const bool fork = (g_s2 != nullptr && g_evA && g_evB && g_evC);
    const int nScanBlocks = (NN + 1023) / 1024;   // 98

    // --- degrees ---
    cudaMemsetAsync(cnt2, 0, 2 * NN * sizeof(int));
    cudaMemsetAsync(cf, 0, NN * sizeof(float));
    hist_kernel<<<(NE + 255) / 256, 256>>>(src, dst, cnt2);

    if (fork) {
        cudaEventRecord(g_evA, 0);
        cudaStreamWaitEvent(g_s2, g_evA, 0);
        // side stream: norms -> (evB) -> conv + prep -> (evC)
        norm_kernel<<<(NN + 255) / 256, 256, 0, g_s2>>>(cnt2, ns, nd);
        cudaEventRecord(g_evB, g_s2);
        conv_kernel<<<(NN * DD / 4 + 255) / 256, 256, 0, g_s2>>>(h, ns, X);
        prep_kernel<<<64, 256, 0, g_s2>>>(W0, W1, Wt0, Wt1);
        cudaEventRecord(g_evC, g_s2);
    } else {
        norm_kernel<<<(NN + 255) / 256, 256>>>(cnt2, ns, nd);
        conv_kernel<<<(NN * DD / 4 + 255) / 256, 256>>>(h, ns, X);
        prep_kernel<<<64, 256>>>(W0, W1, Wt0, Wt1);
    }

    // --- CSR chain on main stream ---
    scan1_kernel<<<nScanBlocks, 256>>>(cnt2 + NN, incl, bsum);
    scan3_kernel<<<nScanBlocks, 256>>>(incl, bsum, cnt2, cur);
    if (fork) cudaStreamWaitEvent(0, g_evB, 0);   // fill needs nd
    fill_kernel<<<(NE + 255) / 256, 256>>>(src, dst, nd, cur, esrc, cf);
    if (fork) cudaStreamWaitEvent(0, g_evC, 0);   // gather0 needs X, gemm needs Wt

    const int gatherBlocks = (NN * 32 + 255) / 256;   // 12500
    const int gemmBlocks   = NN_PAD / 128;            // 782

    // --- layer 0: X -gather-> AGG -gemm-> Y ---
    gather_kernel<<<gatherBlocks, 256>>>(X, nd, incl, cnt2, esrc, AGG);
    gemm_f16_kernel<0><<<gemmBlocks, 256, gemmSmem>>>(AGG, Wt0, b0, ns, cf, Y, vec);

    // --- layer 1 + folded layer 2: Y -gather-> AGG -gemm+reduce-> vec ---
    gather_kernel<<<gatherBlocks, 256>>>(Y, nd, incl, cnt2, esrc, AGG);
    cudaMemsetAsync(vec, 0, DD * sizeof(float));
    gemm_f16_kernel<1><<<gemmBlocks, 256, gemmSmem>>>(AGG, Wt1, b1, ns, cf, X, vec);

    // --- out = (vec/N) @ W2 + b2 ---
    final_kernel<<<1, DD>>>(W2, b2, vec, out);

    (void)in_sizes; (void)n_in; (void)out_size;
}